// round 13
// baseline (speedup 1.0000x reference)
#include <cuda_runtime.h>
#include <cuda_bf16.h>
#include <math.h>

#define BB   4
#define LL   1024
#define HIDD 768
#define HH   12
#define DD   64
#define BH   (BB*HH)

// ---- scratch (device globals; no allocation allowed) ----
__device__ float g_q[BH * LL * DD];                        // [bh, l, d] tf32 bits (pre-scaled 0.125)
__device__ float g_k[BH * LL * DD];                        // [bh, l, d] tf32 bits
__device__ float g_v[BH * LL * DD];                        // [bh, l, d] tf32 bits
__device__ __nv_bfloat16 g_biasq[(size_t)BH * LL * LL];    // [bh, l, r] = qS/8 + mask
__device__ __nv_bfloat16 g_biaskT[(size_t)BH * LL * LL];   // [bh, r, l] = kS/8

// ---------------- helpers ----------------
__device__ __forceinline__ unsigned tf32cvt(float x) {
    unsigned u;
    asm("cvt.rna.tf32.f32 %0, %1;" : "=r"(u) : "f"(x));
    return u;
}
__device__ __forceinline__ void mma_tf32(float& c0, float& c1, float& c2, float& c3,
                                         unsigned a0, unsigned a1, unsigned a2, unsigned a3,
                                         unsigned b0, unsigned b1) {
    asm("mma.sync.aligned.m16n8k8.row.col.f32.tf32.tf32.f32 "
        "{%0,%1,%2,%3},{%4,%5,%6,%7},{%8,%9},{%0,%1,%2,%3};"
        : "+f"(c0), "+f"(c1), "+f"(c2), "+f"(c3)
        : "r"(a0), "r"(a1), "r"(a2), "r"(a3), "r"(b0), "r"(b1));
}
__device__ __forceinline__ void cp16(const void* smem_dst, const void* gsrc) {
    unsigned sa = (unsigned)__cvta_generic_to_shared(smem_dst);
    asm volatile("cp.async.cg.shared.global [%0], [%1], 16;" :: "r"(sa), "l"(gsrc));
}
__device__ __forceinline__ float2 bf2(unsigned u) {
    __nv_bfloat162 h = *reinterpret_cast<__nv_bfloat162*>(&u);
    return __bfloat1622float2(h);
}
__device__ __forceinline__ unsigned s2u(const void* p) {
    return (unsigned)__cvta_generic_to_shared(p);
}
// ldmatrix x4: four 8x4-tf32 tiles; lane L supplies address for tile L>>3, row L&7.
__device__ __forceinline__ void ldsm4(unsigned& r0, unsigned& r1, unsigned& r2, unsigned& r3,
                                      unsigned saddr) {
    asm volatile("ldmatrix.sync.aligned.m8n8.x4.shared.b16 {%0,%1,%2,%3}, [%4];"
        : "=r"(r0), "=r"(r1), "=r"(r2), "=r"(r3) : "r"(saddr));
}

// ============================================================================
// K1: QKV projection, tf32 mma, register double-buffered staging.
// Outputs stored as tf32-bit floats (consumers do zero conversions).
// ============================================================================
__global__ __launch_bounds__(256) void qkv_mma_kernel(
    const float* __restrict__ X,
    const float* __restrict__ W,
    const float* __restrict__ bias,
    int which)
{
    __shared__ __align__(16) unsigned Xs[64][68];
    __shared__ __align__(16) unsigned Ws[64][68];

    const int tid  = threadIdx.x;
    const int warp = tid >> 5;
    const int lane = tid & 31;
    const int m0 = blockIdx.x * 64;
    const int n0 = blockIdx.y * 64;
    const int mstrip = (warp & 3) * 16;
    const int nh     = (warp >> 2) * 32;

    float acc[4][4];
#pragma unroll
    for (int i = 0; i < 4; i++)
#pragma unroll
        for (int j = 0; j < 4; j++) acc[i][j] = 0.f;

    float4 xr[4], wr[4];
#pragma unroll
    for (int i = 0; i < 4; i++) {
        const int idx = tid + i * 256;
        const int row = idx >> 4;
        const int c4  = idx & 15;
        xr[i] = *(const float4*)(X + (size_t)(m0 + row) * HIDD + c4 * 4);
        wr[i] = *(const float4*)(W + (size_t)(n0 + row) * HIDD + c4 * 4);
    }

    // ldmatrix per-thread bases (A tiles: rowhalf=(lane>>3)&1, khalf=(lane>>4)&1;
    // B pair tiles: rowhalf=(lane>>4)&1, khalf=(lane>>3)&1)
    const unsigned a_lm = s2u(&Xs[mstrip + ((lane >> 3) & 1) * 8 + (lane & 7)]
                                 [((lane >> 4) & 1) * 4]);
    unsigned b_lm[2];
#pragma unroll
    for (int p = 0; p < 2; p++)
        b_lm[p] = s2u(&Ws[nh + p * 16 + ((lane >> 4) & 1) * 8 + (lane & 7)]
                         [((lane >> 3) & 1) * 4]);

    for (int k0 = 0; k0 < HIDD; k0 += 64) {
        __syncthreads();
#pragma unroll
        for (int i = 0; i < 4; i++) {
            const int idx = tid + i * 256;
            const int row = idx >> 4;
            const int c4  = idx & 15;
            Xs[row][c4 * 4 + 0] = tf32cvt(xr[i].x); Xs[row][c4 * 4 + 1] = tf32cvt(xr[i].y);
            Xs[row][c4 * 4 + 2] = tf32cvt(xr[i].z); Xs[row][c4 * 4 + 3] = tf32cvt(xr[i].w);
            Ws[row][c4 * 4 + 0] = tf32cvt(wr[i].x); Ws[row][c4 * 4 + 1] = tf32cvt(wr[i].y);
            Ws[row][c4 * 4 + 2] = tf32cvt(wr[i].z); Ws[row][c4 * 4 + 3] = tf32cvt(wr[i].w);
        }
        __syncthreads();
        if (k0 + 64 < HIDD) {
#pragma unroll
            for (int i = 0; i < 4; i++) {
                const int idx = tid + i * 256;
                const int row = idx >> 4;
                const int c4  = idx & 15;
                xr[i] = *(const float4*)(X + (size_t)(m0 + row) * HIDD + k0 + 64 + c4 * 4);
                wr[i] = *(const float4*)(W + (size_t)(n0 + row) * HIDD + k0 + 64 + c4 * 4);
            }
        }
#pragma unroll
        for (int ks = 0; ks < 8; ks++) {
            unsigned a0, a1, a2, a3;
            ldsm4(a0, a1, a2, a3, a_lm + ks * 32);
#pragma unroll
            for (int p = 0; p < 2; p++) {
                unsigned b0, b1, c0, c1;
                ldsm4(b0, b1, c0, c1, b_lm[p] + ks * 32);
                mma_tf32(acc[2 * p][0], acc[2 * p][1], acc[2 * p][2], acc[2 * p][3],
                         a0, a1, a2, a3, b0, b1);
                mma_tf32(acc[2 * p + 1][0], acc[2 * p + 1][1], acc[2 * p + 1][2], acc[2 * p + 1][3],
                         a0, a1, a2, a3, c0, c1);
            }
        }
    }

    float* out = (which == 0) ? g_q : (which == 1) ? g_k : g_v;
    const float scale = (which == 0) ? 0.125f : 1.0f;
    const int row0 = m0 + mstrip + (lane >> 2);
#pragma unroll
    for (int nt = 0; nt < 4; nt++) {
        const int col = n0 + nh + nt * 8 + 2 * (lane & 3);
        const int h = col >> 6;
        const int d = col & 63;
#pragma unroll
        for (int half = 0; half < 2; half++) {
            const int row = row0 + half * 8;
            const int b_idx = row >> 10;
            const int l     = row & (LL - 1);
            float2 r;
            r.x = __uint_as_float(tf32cvt((acc[nt][2 * half + 0] + bias[col + 0]) * scale));
            r.y = __uint_as_float(tf32cvt((acc[nt][2 * half + 1] + bias[col + 1]) * scale));
            *(float2*)&out[(((size_t)b_idx * HH + h) * LL + l) * DD + d] = r;
        }
    }
}

// ============================================================================
// K2: combined structure-bias GEMM (L2 supertiled), ldmatrix fragment loads.
// grid = (2048, 8): y = l-supertile.
//   x < 1024  -> variant 0: f = y*128 + (x>>3),  n0 = (x&7)*128
//   x >= 1024 -> variant 1: f = x - 1024,        n0 = y*128
// ============================================================================
#define STGW 136   // staging stride in bf16

__global__ __launch_bounds__(256) void bias_mma_kernel(
    const float* __restrict__ S, const float* __restrict__ mask)
{
    __shared__ __align__(16) unsigned As[64][68];
    __shared__ __align__(16) unsigned Ss[128][68];   // reused as bf16 staging

    const int tid  = threadIdx.x;
    const int warp = tid >> 5;
    const int lane = tid & 31;

    const int x    = blockIdx.x;
    const int ysup = blockIdx.y;
    int variant, f, n0;
    if (x < 1024) { variant = 0; f = ysup * 128 + (x >> 3); n0 = (x & 7) * 128; }
    else          { variant = 1; f = x - 1024;              n0 = ysup * 128;    }

    const int nh   = (warp >> 2) * 64;
    const int mstrip = (warp & 3) * 16;
    const int arow = mstrip + (lane >> 2);

    const float* Aop = (variant == 0) ? g_q : g_k;

    // A tile: 48 real bh rows (zero-pad to 64), already tf32 bits
#pragma unroll
    for (int i = 0; i < 4; i++) {
        const int idx = tid + i * 256;
        const int row = idx >> 4;
        const int c4  = idx & 15;
        if (row < BH) {
            float4 av = *(const float4*)(Aop + ((size_t)row * LL + f) * DD + c4 * 4);
            As[row][c4 * 4 + 0] = __float_as_uint(av.x);
            As[row][c4 * 4 + 1] = __float_as_uint(av.y);
            As[row][c4 * 4 + 2] = __float_as_uint(av.z);
            As[row][c4 * 4 + 3] = __float_as_uint(av.w);
        } else {
            As[row][c4 * 4 + 0] = 0u; As[row][c4 * 4 + 1] = 0u;
            As[row][c4 * 4 + 2] = 0u; As[row][c4 * 4 + 3] = 0u;
        }
    }
    // S tile: 128 n rows
#pragma unroll
    for (int i = 0; i < 8; i++) {
        const int idx = tid + i * 256;
        const int row = idx >> 4;
        const int c4  = idx & 15;
        size_t soff = (variant == 0)
            ? (((size_t)f * LL + n0 + row) * DD + c4 * 4)
            : (((size_t)(n0 + row) * LL + f) * DD + c4 * 4);
        float4 sv = *(const float4*)(S + soff);
        Ss[row][c4 * 4 + 0] = tf32cvt(sv.x); Ss[row][c4 * 4 + 1] = tf32cvt(sv.y);
        Ss[row][c4 * 4 + 2] = tf32cvt(sv.z); Ss[row][c4 * 4 + 3] = tf32cvt(sv.w);
    }
    __syncthreads();

    float acc[8][4];
#pragma unroll
    for (int i = 0; i < 8; i++)
#pragma unroll
        for (int j = 0; j < 4; j++) acc[i][j] = 0.f;

    // ldmatrix bases
    const unsigned a_lm = s2u(&As[mstrip + ((lane >> 3) & 1) * 8 + (lane & 7)]
                                 [((lane >> 4) & 1) * 4]);
    unsigned b_lm[4];
#pragma unroll
    for (int p = 0; p < 4; p++)
        b_lm[p] = s2u(&Ss[nh + p * 16 + ((lane >> 4) & 1) * 8 + (lane & 7)]
                         [((lane >> 3) & 1) * 4]);

#pragma unroll
    for (int ks = 0; ks < 8; ks++) {
        unsigned a0, a1, a2, a3;
        ldsm4(a0, a1, a2, a3, a_lm + ks * 32);
#pragma unroll
        for (int p = 0; p < 4; p++) {
            unsigned b0, b1, c0, c1;
            ldsm4(b0, b1, c0, c1, b_lm[p] + ks * 32);
            mma_tf32(acc[2 * p][0], acc[2 * p][1], acc[2 * p][2], acc[2 * p][3],
                     a0, a1, a2, a3, b0, b1);
            mma_tf32(acc[2 * p + 1][0], acc[2 * p + 1][1], acc[2 * p + 1][2], acc[2 * p + 1][3],
                     a0, a1, a2, a3, c0, c1);
        }
    }
    __syncthreads();   // all mma reads of Ss done; reuse as staging

    // ---- stage bf16 results ----
    __nv_bfloat16* stg = (__nv_bfloat16*)&Ss[0][0];
#pragma unroll
    for (int nt = 0; nt < 8; nt++) {
        const int col = nh + nt * 8 + 2 * (lane & 3);
#pragma unroll
        for (int half = 0; half < 2; half++) {
            const int bh = arow + half * 8;
            if (bh >= BH) continue;
            __nv_bfloat162 bv;
            if (variant == 0) {
                const int b_idx = bh / HH;
                bv = __floats2bfloat162_rn(
                    acc[nt][2 * half + 0] + mask[b_idx * LL + n0 + col + 0],
                    acc[nt][2 * half + 1] + mask[b_idx * LL + n0 + col + 1]);
            } else {
                bv = __floats2bfloat162_rn(
                    acc[nt][2 * half + 0] * 0.125f,
                    acc[nt][2 * half + 1] * 0.125f);
            }
            *(__nv_bfloat162*)&stg[bh * STGW + col] = bv;
        }
    }
    __syncthreads();

    // ---- coalesced store: 48 rows x 256B contiguous ----
    __nv_bfloat16* dst_base = (variant == 0) ? g_biasq : g_biaskT;
#pragma unroll
    for (int i = 0; i < 3; i++) {
        const int idx = tid + i * 256;
        const int row = idx >> 4;             // bh 0..47
        const int seg = idx & 15;
        uint4 v = *(const uint4*)&stg[row * STGW + seg * 8];
        *(uint4*)&dst_base[((size_t)row * LL + f) * LL + n0 + seg * 8] = v;
    }
}

// ============================================================================
// K3: fused flash attention.  75.8 KB smem, forced 3 CTAs/SM.
// qk mma uses ldmatrix fragments; PV unchanged.
// ============================================================================
#define RC      32
#define SPW     36
#define QSW     68

// smem layout (float units)
#define OFF_QS    0
#define OFF_KS0   4352
#define OFF_KS1   6528
#define OFF_VH0   8704
#define OFF_VH1   10880
#define OFF_SP    13056
#define OFF_PL    15360
#define OFF_TS    17664
#define OFF_MS    18752
#define OFF_SU    18816
#define OFF_SC    18880
#define SMEM_FLOATS 18944                 // 75776 B

__global__ __launch_bounds__(256, 3) void fused_attn_kernel(float* __restrict__ out)
{
    extern __shared__ float sm[];
    float* Qs = sm + OFF_QS;
    float* Sp = sm + OFF_SP;
    float* Pl = sm + OFF_PL;
    float* m_state   = sm + OFF_MS;
    float* sum_state = sm + OFF_SU;
    float* scalef    = sm + OFF_SC;

    const int tid  = threadIdx.x;
    const int lane = tid & 31;
    const int warp = tid >> 5;
    const int bh   = blockIdx.y;
    const int l0   = blockIdx.x * 64;

    const int mstrip = (warp & 3) * 16;
    const int nh2    = (warp >> 2) * 16;
    const int nhpv   = (warp >> 2) * 32;
    const int arow   = mstrip + (lane >> 2);
    const int kcl    = lane & 3;

    // ---- prologue: Q tile (tf32 bits) -> smem ----
#pragma unroll
    for (int i = 0; i < 4; i++) {
        const int idx = tid + i * 256;
        const int row = idx >> 4;
        const int c4  = idx & 15;
        *(float4*)&Qs[row * QSW + c4 * 4] =
            *(const float4*)(g_q + ((size_t)bh * LL + l0 + row) * DD + c4 * 4);
    }
    if (tid < 64) { m_state[tid] = -1e30f; sum_state[tid] = 0.f; }

    const int krow = tid >> 4, kseg = tid & 15;
    const int trow = tid >> 3, tseg = tid & 7;
    const int bql  = tid >> 2, bqc  = (tid & 3) * 8;

    // ldmatrix per-thread row/col offsets
    const int a_lm_row = mstrip + ((lane >> 3) & 1) * 8 + (lane & 7);
    const int a_lm_col = ((lane >> 4) & 1) * 4;
    const int b_lm_row = nh2 + ((lane >> 4) & 1) * 8 + (lane & 7);
    const int b_lm_col = ((lane >> 3) & 1) * 4;
    const unsigned qa_lm = s2u(&Qs[a_lm_row * QSW + a_lm_col]);

    auto stage = [&](int rc, int db) {
        float* Ks = sm + (db ? OFF_KS1 : OFF_KS0);
        float* Vh = sm + (db ? OFF_VH1 : OFF_VH0);
#pragma unroll
        for (int i = 0; i < 2; i++) {
            const int row = krow + i * 16;
            const size_t goff = ((size_t)bh * LL + rc + row) * DD + kseg * 4;
            cp16(&Ks[row * QSW + kseg * 4], g_k + goff);
            cp16(&Vh[row * QSW + kseg * 4], g_v + goff);
        }
        asm volatile("cp.async.commit_group;" ::: "memory");
    };
    auto ldg_ts = [&](int rc) -> uint4 {
        return *(const uint4*)(g_biaskT + ((size_t)bh * LL + rc + trow) * LL + l0 + tseg * 8);
    };
    auto ldg_bq = [&](int rc) -> uint4 {
        return *(const uint4*)(g_biasq + ((size_t)bh * LL + l0 + bql) * LL + rc + bqc);
    };

    float accpv[4][4];
#pragma unroll
    for (int i = 0; i < 4; i++)
#pragma unroll
        for (int j = 0; j < 4; j++) accpv[i][j] = 0.f;

    uint4 ts_reg = ldg_ts(0);
    uint4 bq_reg = ldg_bq(0);
    stage(0, 0);

    for (int ci = 0; ci < LL / RC; ci++) {
        const int cur = ci & 1;
        float* Ks = sm + (cur ? OFF_KS1 : OFF_KS0);
        float* Vh = sm + (cur ? OFF_VH1 : OFF_VH0);
        unsigned short* TsL = (unsigned short*)(sm + OFF_TS);

        // TsL writes safe pre-barrier (prior chunk's stats reads completed
        // before its pre-PV sync, which every thread has passed).
        {
            const unsigned short* h = (const unsigned short*)&ts_reg;
#pragma unroll
            for (int j = 0; j < 8; j++)
                TsL[(tseg * 8 + j) * 34 + trow] = h[j];
        }

        asm volatile("cp.async.wait_group 0;" ::: "memory");
        __syncthreads();

        uint4 ts_next, bq_next;
        if (ci + 1 < LL / RC) {
            ts_next = ldg_ts((ci + 1) * RC);
            bq_next = ldg_bq((ci + 1) * RC);
            stage((ci + 1) * RC, cur ^ 1);
        }

        // ---- qk mma via ldmatrix ----
        float accqk[2][4];
#pragma unroll
        for (int i = 0; i < 2; i++)
#pragma unroll
            for (int j = 0; j < 4; j++) accqk[i][j] = 0.f;
        const unsigned kb_lm = s2u(&Ks[b_lm_row * QSW + b_lm_col]);
#pragma unroll
        for (int ks = 0; ks < 8; ks++) {
            unsigned a0, a1, a2, a3, b0, b1, c0, c1;
            ldsm4(a0, a1, a2, a3, qa_lm + ks * 32);
            ldsm4(b0, b1, c0, c1, kb_lm + ks * 32);
            mma_tf32(accqk[0][0], accqk[0][1], accqk[0][2], accqk[0][3],
                     a0, a1, a2, a3, b0, b1);
            mma_tf32(accqk[1][0], accqk[1][1], accqk[1][2], accqk[1][3],
                     a0, a1, a2, a3, c0, c1);
        }
#pragma unroll
        for (int nt = 0; nt < 2; nt++) {
            const int col = nh2 + nt * 8 + 2 * (lane & 3);
#pragma unroll
            for (int half = 0; half < 2; half++) {
                const int row = arow + half * 8;
                *(float2*)&Sp[row * SPW + col] =
                    make_float2(accqk[nt][2 * half + 0], accqk[nt][2 * half + 1]);
            }
        }
        __syncthreads();                    // Sp + TsL ready

        // ---- merged stats + P ----
        {
            const int l  = bql;
            const int c0 = bqc;
            const float mv_old = m_state[l];
            float s[8];
            {
                float4 sp0 = *(float4*)&Sp[l * SPW + c0];
                float4 sp1 = *(float4*)&Sp[l * SPW + c0 + 4];
                const __nv_bfloat162* ts2 = (const __nv_bfloat162*)&TsL[l * 34 + c0];
                float2 b0 = bf2(bq_reg.x);
                float2 b1 = bf2(bq_reg.y);
                float2 b2 = bf2(bq_reg.z);
                float2 b3 = bf2(bq_reg.w);
                float2 t0 = __bfloat1622float2(ts2[0]);
                float2 t1 = __bfloat1622float2(ts2[1]);
                float2 t2 = __bfloat1622float2(ts2[2]);
                float2 t3 = __bfloat1622float2(ts2[3]);
                s[0] = sp0.x + b0.x + t0.x;  s[1] = sp0.y + b0.y + t0.y;
                s[2] = sp0.z + b1.x + t1.x;  s[3] = sp0.w + b1.y + t1.y;
                s[4] = sp1.x + b2.x + t2.x;  s[5] = sp1.y + b2.y + t2.y;
                s[6] = sp1.z + b3.x + t3.x;  s[7] = sp1.w + b3.y + t3.y;
            }
            float mc = s[0];
#pragma unroll
            for (int j = 1; j < 8; j++) mc = fmaxf(mc, s[j]);
            mc = fmaxf(mc, __shfl_xor_sync(0xffffffffu, mc, 1));
            mc = fmaxf(mc, __shfl_xor_sync(0xffffffffu, mc, 2));
            const float mnew = fmaxf(mv_old, mc);
            float e = 0.f;
            float pv[8], ph[8];
#pragma unroll
            for (int j = 0; j < 8; j++) {
                pv[j] = __expf(s[j] - mnew);
                e += pv[j];
                ph[j] = __uint_as_float(tf32cvt(pv[j]));
            }
            float4 p0, p1, q0, q1;
            p0.x = ph[0]; p0.y = ph[1]; p0.z = ph[2]; p0.w = ph[3];
            p1.x = ph[4]; p1.y = ph[5]; p1.z = ph[6]; p1.w = ph[7];
            q0.x = __uint_as_float(tf32cvt(pv[0] - ph[0]));
            q0.y = __uint_as_float(tf32cvt(pv[1] - ph[1]));
            q0.z = __uint_as_float(tf32cvt(pv[2] - ph[2]));
            q0.w = __uint_as_float(tf32cvt(pv[3] - ph[3]));
            q1.x = __uint_as_float(tf32cvt(pv[4] - ph[4]));
            q1.y = __uint_as_float(tf32cvt(pv[5] - ph[5]));
            q1.z = __uint_as_float(tf32cvt(pv[6] - ph[6]));
            q1.w = __uint_as_float(tf32cvt(pv[7] - ph[7]));
            *(float4*)&Sp[l * SPW + c0]     = p0;
            *(float4*)&Sp[l * SPW + c0 + 4] = p1;
            *(float4*)&Pl[l * SPW + c0]     = q0;
            *(float4*)&Pl[l * SPW + c0 + 4] = q1;
            e += __shfl_xor_sync(0xffffffffu, e, 1);
            e += __shfl_xor_sync(0xffffffffu, e, 2);
            if ((tid & 3) == 0) {
                const float sc = __expf(mv_old - mnew);
                scalef[l] = sc;
                sum_state[l] = sum_state[l] * sc + e;
                m_state[l] = mnew;
            }
        }
        __syncthreads();                    // P + scalef ready

        // ---- rescale + P-compensated P@V mma ----
        {
            const float sc0 = scalef[arow];
            const float sc1 = scalef[arow + 8];
#pragma unroll
            for (int nt = 0; nt < 4; nt++) {
                accpv[nt][0] *= sc0; accpv[nt][1] *= sc0;
                accpv[nt][2] *= sc1; accpv[nt][3] *= sc1;
            }
        }
#pragma unroll
        for (int ks = 0; ks < 4; ks++) {
            const int kc = ks * 8 + kcl;
            unsigned ah0 = __float_as_uint(Sp[arow * SPW + kc]);
            unsigned ah1 = __float_as_uint(Sp[(arow + 8) * SPW + kc]);
            unsigned ah2 = __float_as_uint(Sp[arow * SPW + kc + 4]);
            unsigned ah3 = __float_as_uint(Sp[(arow + 8) * SPW + kc + 4]);
            unsigned al0 = __float_as_uint(Pl[arow * SPW + kc]);
            unsigned al1 = __float_as_uint(Pl[(arow + 8) * SPW + kc]);
            unsigned al2 = __float_as_uint(Pl[arow * SPW + kc + 4]);
            unsigned al3 = __float_as_uint(Pl[(arow + 8) * SPW + kc + 4]);
#pragma unroll
            for (int nt = 0; nt < 4; nt++) {
                const int nb = nhpv + nt * 8 + (lane >> 2);
                unsigned bh0 = __float_as_uint(Vh[(ks * 8 + kcl) * QSW + nb]);
                unsigned bh1 = __float_as_uint(Vh[(ks * 8 + kcl + 4) * QSW + nb]);
                mma_tf32(accpv[nt][0], accpv[nt][1], accpv[nt][2], accpv[nt][3],
                         ah0, ah1, ah2, ah3, bh0, bh1);
                mma_tf32(accpv[nt][0], accpv[nt][1], accpv[nt][2], accpv[nt][3],
                         al0, al1, al2, al3, bh0, bh1);
            }
        }
        ts_reg = ts_next;
        bq_reg = bq_next;
    }

    // ---- write out[b, l, h*64 + d] ----
    const int b_idx = bh / HH;
    const int h     = bh % HH;
#pragma unroll
    for (int half = 0; half < 2; half++) {
        const int row = arow + half * 8;
        const float inv = 1.f / sum_state[row];
        const int l = l0 + row;
#pragma unroll
        for (int nt = 0; nt < 4; nt++) {
            const int col = nhpv + nt * 8 + 2 * (lane & 3);
            float2 r;
            r.x = accpv[nt][2 * half + 0] * inv;
            r.y = accpv[nt][2 * half + 1] * inv;
            *(float2*)&out[((size_t)(b_idx * LL + l)) * HIDD + h * DD + col] = r;
        }
    }
}

// ============================================================================
// launch — q || k || v projections; combined bias after (q,k); fused after all.
// ============================================================================
extern "C" void kernel_launch(void* const* d_in, const int* in_sizes, int n_in,
                              void* d_out, int out_size)
{
    (void)in_sizes; (void)n_in; (void)out_size;
    const float* hidden = (const float*)d_in[0];
    const float* mask   = (const float*)d_in[1];
    const float* S      = (const float*)d_in[2];
    const float* Wq     = (const float*)d_in[3];
    const float* bq     = (const float*)d_in[4];
    const float* Wk     = (const float*)d_in[5];
    const float* bk     = (const float*)d_in[6];
    const float* Wv     = (const float*)d_in[7];
    const float* bv     = (const float*)d_in[8];
    float* out = (float*)d_out;

    static cudaStream_t s1 = 0, s2 = 0;
    static cudaEvent_t eR = 0, e1 = 0, e2 = 0;
    static int init_done = 0;
    if (!init_done) {
        cudaFuncSetAttribute(fused_attn_kernel,
                             cudaFuncAttributeMaxDynamicSharedMemorySize,
                             SMEM_FLOATS * (int)sizeof(float));
        cudaStreamCreateWithFlags(&s1, cudaStreamNonBlocking);
        cudaStreamCreateWithFlags(&s2, cudaStreamNonBlocking);
        cudaEventCreateWithFlags(&eR, cudaEventDisableTiming);
        cudaEventCreateWithFlags(&e1, cudaEventDisableTiming);
        cudaEventCreateWithFlags(&e2, cudaEventDisableTiming);
        init_done = 1;
    }

    dim3 g1(64, 12);

    cudaEventRecord(eR, 0);
    cudaStreamWaitEvent(s1, eR, 0);
    cudaStreamWaitEvent(s2, eR, 0);

    // projections: q on stream 0, k on s1, v on s2
    qkv_mma_kernel<<<g1, 256, 0, 0>>>(hidden, Wq, bq, 0);
    qkv_mma_kernel<<<g1, 256, 0, s1>>>(hidden, Wk, bk, 1);
    qkv_mma_kernel<<<g1, 256, 0, s2>>>(hidden, Wv, bv, 2);

    // bias needs q AND k
    cudaEventRecord(e1, s1);
    cudaStreamWaitEvent(0, e1, 0);
    dim3 g2(2048, 8);
    bias_mma_kernel<<<g2, 256, 0, 0>>>(S, mask);

    // fused needs everything
    cudaEventRecord(e2, s2);
    cudaStreamWaitEvent(0, e2, 0);
    dim3 g3(16, 48);
    fused_attn_kernel<<<g3, 256, SMEM_FLOATS * sizeof(float)>>>(out);
}

// round 14
// speedup vs baseline: 1.0037x; 1.0037x over previous
#include <cuda_runtime.h>
#include <cuda_bf16.h>
#include <math.h>

#define BB   4
#define LL   1024
#define HIDD 768
#define HH   12
#define DD   64
#define BH   (BB*HH)

// ---- scratch (device globals; no allocation allowed) ----
__device__ float g_q[BH * LL * DD];                        // [bh, l, d] tf32 bits (pre-scaled 0.125)
__device__ float g_k[BH * LL * DD];                        // [bh, l, d] tf32 bits
__device__ float g_v[BH * LL * DD];                        // [bh, l, d] tf32 bits
__device__ __nv_bfloat16 g_biasq[(size_t)BH * LL * LL];    // [bh, l, r] = qS/8 + mask
__device__ __nv_bfloat16 g_biaskT[(size_t)BH * LL * LL];   // [bh, r, l] = kS/8

// ---------------- helpers ----------------
__device__ __forceinline__ unsigned tf32cvt(float x) {
    unsigned u;
    asm("cvt.rna.tf32.f32 %0, %1;" : "=r"(u) : "f"(x));
    return u;
}
__device__ __forceinline__ void mma_tf32(float& c0, float& c1, float& c2, float& c3,
                                         unsigned a0, unsigned a1, unsigned a2, unsigned a3,
                                         unsigned b0, unsigned b1) {
    asm("mma.sync.aligned.m16n8k8.row.col.f32.tf32.tf32.f32 "
        "{%0,%1,%2,%3},{%4,%5,%6,%7},{%8,%9},{%0,%1,%2,%3};"
        : "+f"(c0), "+f"(c1), "+f"(c2), "+f"(c3)
        : "r"(a0), "r"(a1), "r"(a2), "r"(a3), "r"(b0), "r"(b1));
}
__device__ __forceinline__ void cp16(const void* smem_dst, const void* gsrc) {
    unsigned sa = (unsigned)__cvta_generic_to_shared(smem_dst);
    asm volatile("cp.async.cg.shared.global [%0], [%1], 16;" :: "r"(sa), "l"(gsrc));
}
__device__ __forceinline__ float2 bf2(unsigned u) {
    __nv_bfloat162 h = *reinterpret_cast<__nv_bfloat162*>(&u);
    return __bfloat1622float2(h);
}
__device__ __forceinline__ unsigned s2u(const void* p) {
    return (unsigned)__cvta_generic_to_shared(p);
}
// ldmatrix x4: four 8x4-tf32 tiles; lane L supplies address for tile L>>3, row L&7.
__device__ __forceinline__ void ldsm4(unsigned& r0, unsigned& r1, unsigned& r2, unsigned& r3,
                                      unsigned saddr) {
    asm volatile("ldmatrix.sync.aligned.m8n8.x4.shared.b16 {%0,%1,%2,%3}, [%4];"
        : "=r"(r0), "=r"(r1), "=r"(r2), "=r"(r3) : "r"(saddr));
}

// ============================================================================
// K1: QKV projection, tf32 mma, register double-buffered staging.
// Outputs stored as tf32-bit floats (consumers do zero conversions).
// ============================================================================
__global__ __launch_bounds__(256) void qkv_mma_kernel(
    const float* __restrict__ X,
    const float* __restrict__ W,
    const float* __restrict__ bias,
    int which)
{
    __shared__ __align__(16) unsigned Xs[64][68];
    __shared__ __align__(16) unsigned Ws[64][68];

    const int tid  = threadIdx.x;
    const int warp = tid >> 5;
    const int lane = tid & 31;
    const int m0 = blockIdx.x * 64;
    const int n0 = blockIdx.y * 64;
    const int mstrip = (warp & 3) * 16;
    const int nh     = (warp >> 2) * 32;

    float acc[4][4];
#pragma unroll
    for (int i = 0; i < 4; i++)
#pragma unroll
        for (int j = 0; j < 4; j++) acc[i][j] = 0.f;

    float4 xr[4], wr[4];
#pragma unroll
    for (int i = 0; i < 4; i++) {
        const int idx = tid + i * 256;
        const int row = idx >> 4;
        const int c4  = idx & 15;
        xr[i] = *(const float4*)(X + (size_t)(m0 + row) * HIDD + c4 * 4);
        wr[i] = *(const float4*)(W + (size_t)(n0 + row) * HIDD + c4 * 4);
    }

    const unsigned a_lm = s2u(&Xs[mstrip + ((lane >> 3) & 1) * 8 + (lane & 7)]
                                 [((lane >> 4) & 1) * 4]);
    unsigned b_lm[2];
#pragma unroll
    for (int p = 0; p < 2; p++)
        b_lm[p] = s2u(&Ws[nh + p * 16 + ((lane >> 4) & 1) * 8 + (lane & 7)]
                         [((lane >> 3) & 1) * 4]);

    for (int k0 = 0; k0 < HIDD; k0 += 64) {
        __syncthreads();
#pragma unroll
        for (int i = 0; i < 4; i++) {
            const int idx = tid + i * 256;
            const int row = idx >> 4;
            const int c4  = idx & 15;
            Xs[row][c4 * 4 + 0] = tf32cvt(xr[i].x); Xs[row][c4 * 4 + 1] = tf32cvt(xr[i].y);
            Xs[row][c4 * 4 + 2] = tf32cvt(xr[i].z); Xs[row][c4 * 4 + 3] = tf32cvt(xr[i].w);
            Ws[row][c4 * 4 + 0] = tf32cvt(wr[i].x); Ws[row][c4 * 4 + 1] = tf32cvt(wr[i].y);
            Ws[row][c4 * 4 + 2] = tf32cvt(wr[i].z); Ws[row][c4 * 4 + 3] = tf32cvt(wr[i].w);
        }
        __syncthreads();
        if (k0 + 64 < HIDD) {
#pragma unroll
            for (int i = 0; i < 4; i++) {
                const int idx = tid + i * 256;
                const int row = idx >> 4;
                const int c4  = idx & 15;
                xr[i] = *(const float4*)(X + (size_t)(m0 + row) * HIDD + k0 + 64 + c4 * 4);
                wr[i] = *(const float4*)(W + (size_t)(n0 + row) * HIDD + k0 + 64 + c4 * 4);
            }
        }
#pragma unroll
        for (int ks = 0; ks < 8; ks++) {
            unsigned a0, a1, a2, a3;
            ldsm4(a0, a1, a2, a3, a_lm + ks * 32);
#pragma unroll
            for (int p = 0; p < 2; p++) {
                unsigned b0, b1, c0, c1;
                ldsm4(b0, b1, c0, c1, b_lm[p] + ks * 32);
                mma_tf32(acc[2 * p][0], acc[2 * p][1], acc[2 * p][2], acc[2 * p][3],
                         a0, a1, a2, a3, b0, b1);
                mma_tf32(acc[2 * p + 1][0], acc[2 * p + 1][1], acc[2 * p + 1][2], acc[2 * p + 1][3],
                         a0, a1, a2, a3, c0, c1);
            }
        }
    }

    float* out = (which == 0) ? g_q : (which == 1) ? g_k : g_v;
    const float scale = (which == 0) ? 0.125f : 1.0f;
    const int row0 = m0 + mstrip + (lane >> 2);
#pragma unroll
    for (int nt = 0; nt < 4; nt++) {
        const int col = n0 + nh + nt * 8 + 2 * (lane & 3);
        const int h = col >> 6;
        const int d = col & 63;
#pragma unroll
        for (int half = 0; half < 2; half++) {
            const int row = row0 + half * 8;
            const int b_idx = row >> 10;
            const int l     = row & (LL - 1);
            float2 r;
            r.x = __uint_as_float(tf32cvt((acc[nt][2 * half + 0] + bias[col + 0]) * scale));
            r.y = __uint_as_float(tf32cvt((acc[nt][2 * half + 1] + bias[col + 1]) * scale));
            *(float2*)&out[(((size_t)b_idx * HH + h) * LL + l) * DD + d] = r;
        }
    }
}

// ============================================================================
// K2: combined structure-bias GEMM (L2 supertiled).
// S staged RAW via cp.async (max MLP, zero reg footprint); tf32 cvt happens
// in-register after ldmatrix.  Stores use __stcs (evict-first).
// grid = (2048, 8): y = l-supertile.
//   x < 1024  -> variant 0: f = y*128 + (x>>3),  n0 = (x&7)*128
//   x >= 1024 -> variant 1: f = x - 1024,        n0 = y*128
// ============================================================================
#define STGW 136   // staging stride in bf16

__global__ __launch_bounds__(256) void bias_mma_kernel(
    const float* __restrict__ S, const float* __restrict__ mask)
{
    __shared__ __align__(16) unsigned As[64][68];
    __shared__ __align__(16) unsigned Ss[128][68];   // raw fp32 S; reused as bf16 staging

    const int tid  = threadIdx.x;
    const int warp = tid >> 5;
    const int lane = tid & 31;

    const int x    = blockIdx.x;
    const int ysup = blockIdx.y;
    int variant, f, n0;
    if (x < 1024) { variant = 0; f = ysup * 128 + (x >> 3); n0 = (x & 7) * 128; }
    else          { variant = 1; f = x - 1024;              n0 = ysup * 128;    }

    const int nh   = (warp >> 2) * 64;
    const int mstrip = (warp & 3) * 16;
    const int arow = mstrip + (lane >> 2);

    const float* Aop = (variant == 0) ? g_q : g_k;

    // ---- S tile via cp.async: 128 rows x 64 floats, raw bits ----
#pragma unroll
    for (int i = 0; i < 8; i++) {
        const int idx = tid + i * 256;
        const int row = idx >> 4;
        const int c4  = idx & 15;
        size_t soff = (variant == 0)
            ? (((size_t)f * LL + n0 + row) * DD + c4 * 4)
            : (((size_t)(n0 + row) * LL + f) * DD + c4 * 4);
        cp16(&Ss[row][c4 * 4], S + soff);
    }
    asm volatile("cp.async.commit_group;" ::: "memory");

    // ---- A tile via LDG (tiny; overlaps the cp.asyncs) ----
#pragma unroll
    for (int i = 0; i < 4; i++) {
        const int idx = tid + i * 256;
        const int row = idx >> 4;
        const int c4  = idx & 15;
        if (row < BH) {
            float4 av = *(const float4*)(Aop + ((size_t)row * LL + f) * DD + c4 * 4);
            As[row][c4 * 4 + 0] = __float_as_uint(av.x);
            As[row][c4 * 4 + 1] = __float_as_uint(av.y);
            As[row][c4 * 4 + 2] = __float_as_uint(av.z);
            As[row][c4 * 4 + 3] = __float_as_uint(av.w);
        } else {
            As[row][c4 * 4 + 0] = 0u; As[row][c4 * 4 + 1] = 0u;
            As[row][c4 * 4 + 2] = 0u; As[row][c4 * 4 + 3] = 0u;
        }
    }

    asm volatile("cp.async.wait_group 0;" ::: "memory");
    __syncthreads();

    float acc[8][4];
#pragma unroll
    for (int i = 0; i < 8; i++)
#pragma unroll
        for (int j = 0; j < 4; j++) acc[i][j] = 0.f;

    // ldmatrix bases
    const unsigned a_lm = s2u(&As[mstrip + ((lane >> 3) & 1) * 8 + (lane & 7)]
                                 [((lane >> 4) & 1) * 4]);
    unsigned b_lm[4];
#pragma unroll
    for (int p = 0; p < 4; p++)
        b_lm[p] = s2u(&Ss[nh + p * 16 + ((lane >> 4) & 1) * 8 + (lane & 7)]
                         [((lane >> 3) & 1) * 4]);

#pragma unroll
    for (int ks = 0; ks < 8; ks++) {
        unsigned a0, a1, a2, a3;
        ldsm4(a0, a1, a2, a3, a_lm + ks * 32);
#pragma unroll
        for (int p = 0; p < 4; p++) {
            unsigned b0, b1, c0, c1;
            ldsm4(b0, b1, c0, c1, b_lm[p] + ks * 32);
            // convert raw fp32 S bits -> tf32 (bit-identical to pre-store cvt)
            b0 = tf32cvt(__uint_as_float(b0)); b1 = tf32cvt(__uint_as_float(b1));
            c0 = tf32cvt(__uint_as_float(c0)); c1 = tf32cvt(__uint_as_float(c1));
            mma_tf32(acc[2 * p][0], acc[2 * p][1], acc[2 * p][2], acc[2 * p][3],
                     a0, a1, a2, a3, b0, b1);
            mma_tf32(acc[2 * p + 1][0], acc[2 * p + 1][1], acc[2 * p + 1][2], acc[2 * p + 1][3],
                     a0, a1, a2, a3, c0, c1);
        }
    }
    __syncthreads();   // all mma reads of Ss done; reuse as staging

    // ---- stage bf16 results ----
    __nv_bfloat16* stg = (__nv_bfloat16*)&Ss[0][0];
#pragma unroll
    for (int nt = 0; nt < 8; nt++) {
        const int col = nh + nt * 8 + 2 * (lane & 3);
#pragma unroll
        for (int half = 0; half < 2; half++) {
            const int bh = arow + half * 8;
            if (bh >= BH) continue;
            __nv_bfloat162 bv;
            if (variant == 0) {
                const int b_idx = bh / HH;
                bv = __floats2bfloat162_rn(
                    acc[nt][2 * half + 0] + mask[b_idx * LL + n0 + col + 0],
                    acc[nt][2 * half + 1] + mask[b_idx * LL + n0 + col + 1]);
            } else {
                bv = __floats2bfloat162_rn(
                    acc[nt][2 * half + 0] * 0.125f,
                    acc[nt][2 * half + 1] * 0.125f);
            }
            *(__nv_bfloat162*)&stg[bh * STGW + col] = bv;
        }
    }
    __syncthreads();

    // ---- coalesced streaming store: 48 rows x 256B contiguous ----
    __nv_bfloat16* dst_base = (variant == 0) ? g_biasq : g_biaskT;
#pragma unroll
    for (int i = 0; i < 3; i++) {
        const int idx = tid + i * 256;
        const int row = idx >> 4;             // bh 0..47
        const int seg = idx & 15;
        uint4 v = *(const uint4*)&stg[row * STGW + seg * 8];
        __stcs((uint4*)&dst_base[((size_t)row * LL + f) * LL + n0 + seg * 8], v);
    }
}

// ============================================================================
// K3: fused flash attention.  75.8 KB smem, forced 3 CTAs/SM.
// qk mma uses ldmatrix fragments; PV unchanged.
// ============================================================================
#define RC      32
#define SPW     36
#define QSW     68

// smem layout (float units)
#define OFF_QS    0
#define OFF_KS0   4352
#define OFF_KS1   6528
#define OFF_VH0   8704
#define OFF_VH1   10880
#define OFF_SP    13056
#define OFF_PL    15360
#define OFF_TS    17664
#define OFF_MS    18752
#define OFF_SU    18816
#define OFF_SC    18880
#define SMEM_FLOATS 18944                 // 75776 B

__global__ __launch_bounds__(256, 3) void fused_attn_kernel(float* __restrict__ out)
{
    extern __shared__ float sm[];
    float* Qs = sm + OFF_QS;
    float* Sp = sm + OFF_SP;
    float* Pl = sm + OFF_PL;
    float* m_state   = sm + OFF_MS;
    float* sum_state = sm + OFF_SU;
    float* scalef    = sm + OFF_SC;

    const int tid  = threadIdx.x;
    const int lane = tid & 31;
    const int warp = tid >> 5;
    const int bh   = blockIdx.y;
    const int l0   = blockIdx.x * 64;

    const int mstrip = (warp & 3) * 16;
    const int nh2    = (warp >> 2) * 16;
    const int nhpv   = (warp >> 2) * 32;
    const int arow   = mstrip + (lane >> 2);
    const int kcl    = lane & 3;

    // ---- prologue: Q tile (tf32 bits) -> smem ----
#pragma unroll
    for (int i = 0; i < 4; i++) {
        const int idx = tid + i * 256;
        const int row = idx >> 4;
        const int c4  = idx & 15;
        *(float4*)&Qs[row * QSW + c4 * 4] =
            *(const float4*)(g_q + ((size_t)bh * LL + l0 + row) * DD + c4 * 4);
    }
    if (tid < 64) { m_state[tid] = -1e30f; sum_state[tid] = 0.f; }

    const int krow = tid >> 4, kseg = tid & 15;
    const int trow = tid >> 3, tseg = tid & 7;
    const int bql  = tid >> 2, bqc  = (tid & 3) * 8;

    const int a_lm_row = mstrip + ((lane >> 3) & 1) * 8 + (lane & 7);
    const int a_lm_col = ((lane >> 4) & 1) * 4;
    const int b_lm_row = nh2 + ((lane >> 4) & 1) * 8 + (lane & 7);
    const int b_lm_col = ((lane >> 3) & 1) * 4;
    const unsigned qa_lm = s2u(&Qs[a_lm_row * QSW + a_lm_col]);

    auto stage = [&](int rc, int db) {
        float* Ks = sm + (db ? OFF_KS1 : OFF_KS0);
        float* Vh = sm + (db ? OFF_VH1 : OFF_VH0);
#pragma unroll
        for (int i = 0; i < 2; i++) {
            const int row = krow + i * 16;
            const size_t goff = ((size_t)bh * LL + rc + row) * DD + kseg * 4;
            cp16(&Ks[row * QSW + kseg * 4], g_k + goff);
            cp16(&Vh[row * QSW + kseg * 4], g_v + goff);
        }
        asm volatile("cp.async.commit_group;" ::: "memory");
    };
    auto ldg_ts = [&](int rc) -> uint4 {
        return *(const uint4*)(g_biaskT + ((size_t)bh * LL + rc + trow) * LL + l0 + tseg * 8);
    };
    auto ldg_bq = [&](int rc) -> uint4 {
        return *(const uint4*)(g_biasq + ((size_t)bh * LL + l0 + bql) * LL + rc + bqc);
    };

    float accpv[4][4];
#pragma unroll
    for (int i = 0; i < 4; i++)
#pragma unroll
        for (int j = 0; j < 4; j++) accpv[i][j] = 0.f;

    uint4 ts_reg = ldg_ts(0);
    uint4 bq_reg = ldg_bq(0);
    stage(0, 0);

    for (int ci = 0; ci < LL / RC; ci++) {
        const int cur = ci & 1;
        float* Ks = sm + (cur ? OFF_KS1 : OFF_KS0);
        float* Vh = sm + (cur ? OFF_VH1 : OFF_VH0);
        unsigned short* TsL = (unsigned short*)(sm + OFF_TS);

        // TsL writes safe pre-barrier (prior chunk's stats reads completed
        // before its pre-PV sync, which every thread has passed).
        {
            const unsigned short* h = (const unsigned short*)&ts_reg;
#pragma unroll
            for (int j = 0; j < 8; j++)
                TsL[(tseg * 8 + j) * 34 + trow] = h[j];
        }

        asm volatile("cp.async.wait_group 0;" ::: "memory");
        __syncthreads();

        uint4 ts_next, bq_next;
        if (ci + 1 < LL / RC) {
            ts_next = ldg_ts((ci + 1) * RC);
            bq_next = ldg_bq((ci + 1) * RC);
            stage((ci + 1) * RC, cur ^ 1);
        }

        // ---- qk mma via ldmatrix ----
        float accqk[2][4];
#pragma unroll
        for (int i = 0; i < 2; i++)
#pragma unroll
            for (int j = 0; j < 4; j++) accqk[i][j] = 0.f;
        const unsigned kb_lm = s2u(&Ks[b_lm_row * QSW + b_lm_col]);
#pragma unroll
        for (int ks = 0; ks < 8; ks++) {
            unsigned a0, a1, a2, a3, b0, b1, c0, c1;
            ldsm4(a0, a1, a2, a3, qa_lm + ks * 32);
            ldsm4(b0, b1, c0, c1, kb_lm + ks * 32);
            mma_tf32(accqk[0][0], accqk[0][1], accqk[0][2], accqk[0][3],
                     a0, a1, a2, a3, b0, b1);
            mma_tf32(accqk[1][0], accqk[1][1], accqk[1][2], accqk[1][3],
                     a0, a1, a2, a3, c0, c1);
        }
#pragma unroll
        for (int nt = 0; nt < 2; nt++) {
            const int col = nh2 + nt * 8 + 2 * (lane & 3);
#pragma unroll
            for (int half = 0; half < 2; half++) {
                const int row = arow + half * 8;
                *(float2*)&Sp[row * SPW + col] =
                    make_float2(accqk[nt][2 * half + 0], accqk[nt][2 * half + 1]);
            }
        }
        __syncthreads();                    // Sp + TsL ready

        // ---- merged stats + P ----
        {
            const int l  = bql;
            const int c0 = bqc;
            const float mv_old = m_state[l];
            float s[8];
            {
                float4 sp0 = *(float4*)&Sp[l * SPW + c0];
                float4 sp1 = *(float4*)&Sp[l * SPW + c0 + 4];
                const __nv_bfloat162* ts2 = (const __nv_bfloat162*)&TsL[l * 34 + c0];
                float2 b0 = bf2(bq_reg.x);
                float2 b1 = bf2(bq_reg.y);
                float2 b2 = bf2(bq_reg.z);
                float2 b3 = bf2(bq_reg.w);
                float2 t0 = __bfloat1622float2(ts2[0]);
                float2 t1 = __bfloat1622float2(ts2[1]);
                float2 t2 = __bfloat1622float2(ts2[2]);
                float2 t3 = __bfloat1622float2(ts2[3]);
                s[0] = sp0.x + b0.x + t0.x;  s[1] = sp0.y + b0.y + t0.y;
                s[2] = sp0.z + b1.x + t1.x;  s[3] = sp0.w + b1.y + t1.y;
                s[4] = sp1.x + b2.x + t2.x;  s[5] = sp1.y + b2.y + t2.y;
                s[6] = sp1.z + b3.x + t3.x;  s[7] = sp1.w + b3.y + t3.y;
            }
            float mc = s[0];
#pragma unroll
            for (int j = 1; j < 8; j++) mc = fmaxf(mc, s[j]);
            mc = fmaxf(mc, __shfl_xor_sync(0xffffffffu, mc, 1));
            mc = fmaxf(mc, __shfl_xor_sync(0xffffffffu, mc, 2));
            const float mnew = fmaxf(mv_old, mc);
            float e = 0.f;
            float pv[8], ph[8];
#pragma unroll
            for (int j = 0; j < 8; j++) {
                pv[j] = __expf(s[j] - mnew);
                e += pv[j];
                ph[j] = __uint_as_float(tf32cvt(pv[j]));
            }
            float4 p0, p1, q0, q1;
            p0.x = ph[0]; p0.y = ph[1]; p0.z = ph[2]; p0.w = ph[3];
            p1.x = ph[4]; p1.y = ph[5]; p1.z = ph[6]; p1.w = ph[7];
            q0.x = __uint_as_float(tf32cvt(pv[0] - ph[0]));
            q0.y = __uint_as_float(tf32cvt(pv[1] - ph[1]));
            q0.z = __uint_as_float(tf32cvt(pv[2] - ph[2]));
            q0.w = __uint_as_float(tf32cvt(pv[3] - ph[3]));
            q1.x = __uint_as_float(tf32cvt(pv[4] - ph[4]));
            q1.y = __uint_as_float(tf32cvt(pv[5] - ph[5]));
            q1.z = __uint_as_float(tf32cvt(pv[6] - ph[6]));
            q1.w = __uint_as_float(tf32cvt(pv[7] - ph[7]));
            *(float4*)&Sp[l * SPW + c0]     = p0;
            *(float4*)&Sp[l * SPW + c0 + 4] = p1;
            *(float4*)&Pl[l * SPW + c0]     = q0;
            *(float4*)&Pl[l * SPW + c0 + 4] = q1;
            e += __shfl_xor_sync(0xffffffffu, e, 1);
            e += __shfl_xor_sync(0xffffffffu, e, 2);
            if ((tid & 3) == 0) {
                const float sc = __expf(mv_old - mnew);
                scalef[l] = sc;
                sum_state[l] = sum_state[l] * sc + e;
                m_state[l] = mnew;
            }
        }
        __syncthreads();                    // P + scalef ready

        // ---- rescale + P-compensated P@V mma ----
        {
            const float sc0 = scalef[arow];
            const float sc1 = scalef[arow + 8];
#pragma unroll
            for (int nt = 0; nt < 4; nt++) {
                accpv[nt][0] *= sc0; accpv[nt][1] *= sc0;
                accpv[nt][2] *= sc1; accpv[nt][3] *= sc1;
            }
        }
#pragma unroll
        for (int ks = 0; ks < 4; ks++) {
            const int kc = ks * 8 + kcl;
            unsigned ah0 = __float_as_uint(Sp[arow * SPW + kc]);
            unsigned ah1 = __float_as_uint(Sp[(arow + 8) * SPW + kc]);
            unsigned ah2 = __float_as_uint(Sp[arow * SPW + kc + 4]);
            unsigned ah3 = __float_as_uint(Sp[(arow + 8) * SPW + kc + 4]);
            unsigned al0 = __float_as_uint(Pl[arow * SPW + kc]);
            unsigned al1 = __float_as_uint(Pl[(arow + 8) * SPW + kc]);
            unsigned al2 = __float_as_uint(Pl[arow * SPW + kc + 4]);
            unsigned al3 = __float_as_uint(Pl[(arow + 8) * SPW + kc + 4]);
#pragma unroll
            for (int nt = 0; nt < 4; nt++) {
                const int nb = nhpv + nt * 8 + (lane >> 2);
                unsigned bh0 = __float_as_uint(Vh[(ks * 8 + kcl) * QSW + nb]);
                unsigned bh1 = __float_as_uint(Vh[(ks * 8 + kcl + 4) * QSW + nb]);
                mma_tf32(accpv[nt][0], accpv[nt][1], accpv[nt][2], accpv[nt][3],
                         ah0, ah1, ah2, ah3, bh0, bh1);
                mma_tf32(accpv[nt][0], accpv[nt][1], accpv[nt][2], accpv[nt][3],
                         al0, al1, al2, al3, bh0, bh1);
            }
        }
        ts_reg = ts_next;
        bq_reg = bq_next;
    }

    // ---- write out[b, l, h*64 + d] ----
    const int b_idx = bh / HH;
    const int h     = bh % HH;
#pragma unroll
    for (int half = 0; half < 2; half++) {
        const int row = arow + half * 8;
        const float inv = 1.f / sum_state[row];
        const int l = l0 + row;
#pragma unroll
        for (int nt = 0; nt < 4; nt++) {
            const int col = nhpv + nt * 8 + 2 * (lane & 3);
            float2 r;
            r.x = accpv[nt][2 * half + 0] * inv;
            r.y = accpv[nt][2 * half + 1] * inv;
            *(float2*)&out[((size_t)(b_idx * LL + l)) * HIDD + h * DD + col] = r;
        }
    }
}

// ============================================================================
// launch — q || k || v projections; combined bias after (q,k); fused after all.
// ============================================================================
extern "C" void kernel_launch(void* const* d_in, const int* in_sizes, int n_in,
                              void* d_out, int out_size)
{
    (void)in_sizes; (void)n_in; (void)out_size;
    const float* hidden = (const float*)d_in[0];
    const float* mask   = (const float*)d_in[1];
    const float* S      = (const float*)d_in[2];
    const float* Wq     = (const float*)d_in[3];
    const float* bq     = (const float*)d_in[4];
    const float* Wk     = (const float*)d_in[5];
    const float* bk     = (const float*)d_in[6];
    const float* Wv     = (const float*)d_in[7];
    const float* bv     = (const float*)d_in[8];
    float* out = (float*)d_out;

    static cudaStream_t s1 = 0, s2 = 0;
    static cudaEvent_t eR = 0, e1 = 0, e2 = 0;
    static int init_done = 0;
    if (!init_done) {
        cudaFuncSetAttribute(fused_attn_kernel,
                             cudaFuncAttributeMaxDynamicSharedMemorySize,
                             SMEM_FLOATS * (int)sizeof(float));
        cudaStreamCreateWithFlags(&s1, cudaStreamNonBlocking);
        cudaStreamCreateWithFlags(&s2, cudaStreamNonBlocking);
        cudaEventCreateWithFlags(&eR, cudaEventDisableTiming);
        cudaEventCreateWithFlags(&e1, cudaEventDisableTiming);
        cudaEventCreateWithFlags(&e2, cudaEventDisableTiming);
        init_done = 1;
    }

    dim3 g1(64, 12);

    cudaEventRecord(eR, 0);
    cudaStreamWaitEvent(s1, eR, 0);
    cudaStreamWaitEvent(s2, eR, 0);

    // projections: q on stream 0, k on s1, v on s2
    qkv_mma_kernel<<<g1, 256, 0, 0>>>(hidden, Wq, bq, 0);
    qkv_mma_kernel<<<g1, 256, 0, s1>>>(hidden, Wk, bk, 1);
    qkv_mma_kernel<<<g1, 256, 0, s2>>>(hidden, Wv, bv, 2);

    // bias needs q AND k
    cudaEventRecord(e1, s1);
    cudaStreamWaitEvent(0, e1, 0);
    dim3 g2(2048, 8);
    bias_mma_kernel<<<g2, 256, 0, 0>>>(S, mask);

    // fused needs everything
    cudaEventRecord(e2, s2);
    cudaStreamWaitEvent(0, e2, 0);
    dim3 g3(16, 48);
    fused_attn_kernel<<<g3, 256, SMEM_FLOATS * sizeof(float)>>>(out);
}

// round 15
// speedup vs baseline: 1.1105x; 1.1065x over previous
#include <cuda_runtime.h>
#include <cuda_bf16.h>
#include <math.h>

#define BB   4
#define LL   1024
#define HIDD 768
#define HH   12
#define DD   64
#define BH   (BB*HH)

// ---- scratch (device globals; no allocation allowed) ----
__device__ float g_q[BH * LL * DD];                        // [bh, l, d] tf32 bits (pre-scaled 0.125)
__device__ float g_k[BH * LL * DD];                        // [bh, l, d] tf32 bits
__device__ float g_v[BH * LL * DD];                        // [bh, l, d] tf32 bits
__device__ __nv_bfloat16 g_biasq[(size_t)BH * LL * LL];    // [bh, l, r] = qS/8 + mask
__device__ __nv_bfloat16 g_biaskT[(size_t)BH * LL * LL];   // [bh, r, l] = kS/8

// ---------------- helpers ----------------
__device__ __forceinline__ unsigned tf32cvt(float x) {
    unsigned u;
    asm("cvt.rna.tf32.f32 %0, %1;" : "=r"(u) : "f"(x));
    return u;
}
__device__ __forceinline__ void mma_tf32(float& c0, float& c1, float& c2, float& c3,
                                         unsigned a0, unsigned a1, unsigned a2, unsigned a3,
                                         unsigned b0, unsigned b1) {
    asm("mma.sync.aligned.m16n8k8.row.col.f32.tf32.tf32.f32 "
        "{%0,%1,%2,%3},{%4,%5,%6,%7},{%8,%9},{%0,%1,%2,%3};"
        : "+f"(c0), "+f"(c1), "+f"(c2), "+f"(c3)
        : "r"(a0), "r"(a1), "r"(a2), "r"(a3), "r"(b0), "r"(b1));
}
__device__ __forceinline__ void cp16(const void* smem_dst, const void* gsrc) {
    unsigned sa = (unsigned)__cvta_generic_to_shared(smem_dst);
    asm volatile("cp.async.cg.shared.global [%0], [%1], 16;" :: "r"(sa), "l"(gsrc));
}
__device__ __forceinline__ float2 bf2(unsigned u) {
    __nv_bfloat162 h = *reinterpret_cast<__nv_bfloat162*>(&u);
    return __bfloat1622float2(h);
}
__device__ __forceinline__ unsigned s2u(const void* p) {
    return (unsigned)__cvta_generic_to_shared(p);
}
// ldmatrix x4: four 8x4-tf32 tiles; lane L supplies address for tile L>>3, row L&7.
__device__ __forceinline__ void ldsm4(unsigned& r0, unsigned& r1, unsigned& r2, unsigned& r3,
                                      unsigned saddr) {
    asm volatile("ldmatrix.sync.aligned.m8n8.x4.shared.b16 {%0,%1,%2,%3}, [%4];"
        : "=r"(r0), "=r"(r1), "=r"(r2), "=r"(r3) : "r"(saddr));
}

// ============================================================================
// K1: QKV projection, tf32 mma, register double-buffered staging.
// Outputs stored as tf32-bit floats (consumers do zero conversions).
// ============================================================================
__global__ __launch_bounds__(256) void qkv_mma_kernel(
    const float* __restrict__ X,
    const float* __restrict__ W,
    const float* __restrict__ bias,
    int which)
{
    __shared__ __align__(16) unsigned Xs[64][68];
    __shared__ __align__(16) unsigned Ws[64][68];

    const int tid  = threadIdx.x;
    const int warp = tid >> 5;
    const int lane = tid & 31;
    const int m0 = blockIdx.x * 64;
    const int n0 = blockIdx.y * 64;
    const int mstrip = (warp & 3) * 16;
    const int nh     = (warp >> 2) * 32;

    float acc[4][4];
#pragma unroll
    for (int i = 0; i < 4; i++)
#pragma unroll
        for (int j = 0; j < 4; j++) acc[i][j] = 0.f;

    float4 xr[4], wr[4];
#pragma unroll
    for (int i = 0; i < 4; i++) {
        const int idx = tid + i * 256;
        const int row = idx >> 4;
        const int c4  = idx & 15;
        xr[i] = *(const float4*)(X + (size_t)(m0 + row) * HIDD + c4 * 4);
        wr[i] = *(const float4*)(W + (size_t)(n0 + row) * HIDD + c4 * 4);
    }

    const unsigned a_lm = s2u(&Xs[mstrip + ((lane >> 3) & 1) * 8 + (lane & 7)]
                                 [((lane >> 4) & 1) * 4]);
    unsigned b_lm[2];
#pragma unroll
    for (int p = 0; p < 2; p++)
        b_lm[p] = s2u(&Ws[nh + p * 16 + ((lane >> 4) & 1) * 8 + (lane & 7)]
                         [((lane >> 3) & 1) * 4]);

    for (int k0 = 0; k0 < HIDD; k0 += 64) {
        __syncthreads();
#pragma unroll
        for (int i = 0; i < 4; i++) {
            const int idx = tid + i * 256;
            const int row = idx >> 4;
            const int c4  = idx & 15;
            Xs[row][c4 * 4 + 0] = tf32cvt(xr[i].x); Xs[row][c4 * 4 + 1] = tf32cvt(xr[i].y);
            Xs[row][c4 * 4 + 2] = tf32cvt(xr[i].z); Xs[row][c4 * 4 + 3] = tf32cvt(xr[i].w);
            Ws[row][c4 * 4 + 0] = tf32cvt(wr[i].x); Ws[row][c4 * 4 + 1] = tf32cvt(wr[i].y);
            Ws[row][c4 * 4 + 2] = tf32cvt(wr[i].z); Ws[row][c4 * 4 + 3] = tf32cvt(wr[i].w);
        }
        __syncthreads();
        if (k0 + 64 < HIDD) {
#pragma unroll
            for (int i = 0; i < 4; i++) {
                const int idx = tid + i * 256;
                const int row = idx >> 4;
                const int c4  = idx & 15;
                xr[i] = *(const float4*)(X + (size_t)(m0 + row) * HIDD + k0 + 64 + c4 * 4);
                wr[i] = *(const float4*)(W + (size_t)(n0 + row) * HIDD + k0 + 64 + c4 * 4);
            }
        }
#pragma unroll
        for (int ks = 0; ks < 8; ks++) {
            unsigned a0, a1, a2, a3;
            ldsm4(a0, a1, a2, a3, a_lm + ks * 32);
#pragma unroll
            for (int p = 0; p < 2; p++) {
                unsigned b0, b1, c0, c1;
                ldsm4(b0, b1, c0, c1, b_lm[p] + ks * 32);
                mma_tf32(acc[2 * p][0], acc[2 * p][1], acc[2 * p][2], acc[2 * p][3],
                         a0, a1, a2, a3, b0, b1);
                mma_tf32(acc[2 * p + 1][0], acc[2 * p + 1][1], acc[2 * p + 1][2], acc[2 * p + 1][3],
                         a0, a1, a2, a3, c0, c1);
            }
        }
    }

    float* out = (which == 0) ? g_q : (which == 1) ? g_k : g_v;
    const float scale = (which == 0) ? 0.125f : 1.0f;
    const int row0 = m0 + mstrip + (lane >> 2);
#pragma unroll
    for (int nt = 0; nt < 4; nt++) {
        const int col = n0 + nh + nt * 8 + 2 * (lane & 3);
        const int h = col >> 6;
        const int d = col & 63;
#pragma unroll
        for (int half = 0; half < 2; half++) {
            const int row = row0 + half * 8;
            const int b_idx = row >> 10;
            const int l     = row & (LL - 1);
            float2 r;
            r.x = __uint_as_float(tf32cvt((acc[nt][2 * half + 0] + bias[col + 0]) * scale));
            r.y = __uint_as_float(tf32cvt((acc[nt][2 * half + 1] + bias[col + 1]) * scale));
            *(float2*)&out[(((size_t)b_idx * HH + h) * LL + l) * DD + d] = r;
        }
    }
}

// ============================================================================
// K2: structure-bias GEMM, 64-wide n tiles (round-11 shape: high occupancy),
// cp.async S staging, ldmatrix fragments, staged coalesced __stcs stores.
//  variant 0 (f=l): g_biasq[bh, f, n]  = q.S[f,n,:] + mask[b,n]
//  variant 1 (f=r): g_biaskT[bh, f, n] = 0.125 * k.S[n,f,:]
// smem 34.8 KB -> 5+ CTAs/SM.
// ============================================================================
#define STGW2 72   // staging stride in bf16 (144 B)

__global__ __launch_bounds__(256, 5) void bias_mma_kernel(
    const float* __restrict__ S, const float* __restrict__ mask, int variant)
{
    __shared__ __align__(16) unsigned As[64][68];
    __shared__ __align__(16) unsigned Ss[64][68];   // raw fp32 S; reused as bf16 staging

    const int tid  = threadIdx.x;
    const int warp = tid >> 5;
    const int lane = tid & 31;
    const int n0 = blockIdx.x * 64;
    const int f  = blockIdx.y;
    const int mstrip = (warp & 3) * 16;
    const int nh     = (warp >> 2) * 32;
    const int arow   = mstrip + (lane >> 2);

    const float* Aop = (variant == 0) ? g_q : g_k;

    // ---- S tile via cp.async: 64 rows x 64 floats, raw bits ----
#pragma unroll
    for (int i = 0; i < 4; i++) {
        const int idx = tid + i * 256;
        const int row = idx >> 4;
        const int c4  = idx & 15;
        size_t soff = (variant == 0)
            ? (((size_t)f * LL + n0 + row) * DD + c4 * 4)
            : (((size_t)(n0 + row) * LL + f) * DD + c4 * 4);
        cp16(&Ss[row][c4 * 4], S + soff);
    }
    asm volatile("cp.async.commit_group;" ::: "memory");

    // ---- A tile via LDG (overlaps cp.asyncs) ----
#pragma unroll
    for (int i = 0; i < 4; i++) {
        const int idx = tid + i * 256;
        const int row = idx >> 4;
        const int c4  = idx & 15;
        if (row < BH) {
            float4 av = *(const float4*)(Aop + ((size_t)row * LL + f) * DD + c4 * 4);
            As[row][c4 * 4 + 0] = __float_as_uint(av.x);
            As[row][c4 * 4 + 1] = __float_as_uint(av.y);
            As[row][c4 * 4 + 2] = __float_as_uint(av.z);
            As[row][c4 * 4 + 3] = __float_as_uint(av.w);
        } else {
            As[row][c4 * 4 + 0] = 0u; As[row][c4 * 4 + 1] = 0u;
            As[row][c4 * 4 + 2] = 0u; As[row][c4 * 4 + 3] = 0u;
        }
    }

    asm volatile("cp.async.wait_group 0;" ::: "memory");
    __syncthreads();

    float acc[4][4];
#pragma unroll
    for (int i = 0; i < 4; i++)
#pragma unroll
        for (int j = 0; j < 4; j++) acc[i][j] = 0.f;

    const unsigned a_lm = s2u(&As[mstrip + ((lane >> 3) & 1) * 8 + (lane & 7)]
                                 [((lane >> 4) & 1) * 4]);
    unsigned b_lm[2];
#pragma unroll
    for (int p = 0; p < 2; p++)
        b_lm[p] = s2u(&Ss[nh + p * 16 + ((lane >> 4) & 1) * 8 + (lane & 7)]
                         [((lane >> 3) & 1) * 4]);

#pragma unroll
    for (int ks = 0; ks < 8; ks++) {
        unsigned a0, a1, a2, a3;
        ldsm4(a0, a1, a2, a3, a_lm + ks * 32);
#pragma unroll
        for (int p = 0; p < 2; p++) {
            unsigned b0, b1, c0, c1;
            ldsm4(b0, b1, c0, c1, b_lm[p] + ks * 32);
            b0 = tf32cvt(__uint_as_float(b0)); b1 = tf32cvt(__uint_as_float(b1));
            c0 = tf32cvt(__uint_as_float(c0)); c1 = tf32cvt(__uint_as_float(c1));
            mma_tf32(acc[2 * p][0], acc[2 * p][1], acc[2 * p][2], acc[2 * p][3],
                     a0, a1, a2, a3, b0, b1);
            mma_tf32(acc[2 * p + 1][0], acc[2 * p + 1][1], acc[2 * p + 1][2], acc[2 * p + 1][3],
                     a0, a1, a2, a3, c0, c1);
        }
    }
    __syncthreads();   // mma reads of Ss done; reuse as staging

    // ---- stage bf16 results: stg[bh][n], stride STGW2 ----
    __nv_bfloat16* stg = (__nv_bfloat16*)&Ss[0][0];
#pragma unroll
    for (int nt = 0; nt < 4; nt++) {
        const int col = nh + nt * 8 + 2 * (lane & 3);
#pragma unroll
        for (int half = 0; half < 2; half++) {
            const int bh = arow + half * 8;
            if (bh >= BH) continue;
            __nv_bfloat162 bv;
            if (variant == 0) {
                const int b_idx = bh / HH;
                bv = __floats2bfloat162_rn(
                    acc[nt][2 * half + 0] + mask[b_idx * LL + n0 + col + 0],
                    acc[nt][2 * half + 1] + mask[b_idx * LL + n0 + col + 1]);
            } else {
                bv = __floats2bfloat162_rn(
                    acc[nt][2 * half + 0] * 0.125f,
                    acc[nt][2 * half + 1] * 0.125f);
            }
            *(__nv_bfloat162*)&stg[bh * STGW2 + col] = bv;
        }
    }
    __syncthreads();

    // ---- coalesced streaming store: 48 rows x 128B contiguous (384 uint4) ----
    __nv_bfloat16* dst_base = (variant == 0) ? g_biasq : g_biaskT;
    if (tid < 192) {
#pragma unroll
        for (int i = 0; i < 2; i++) {
            const int idx = tid + i * 192;        // 0..383
            const int row = idx >> 3;             // bh 0..47
            const int seg = idx & 7;              // 8 x 8 bf16 = 64 cols
            uint4 v = *(const uint4*)&stg[row * STGW2 + seg * 8];
            __stcs((uint4*)&dst_base[((size_t)row * LL + f) * LL + n0 + seg * 8], v);
        }
    }
}

// ============================================================================
// K3: fused flash attention.  66.5 KB smem, 3 CTAs/SM.
// qk via ldmatrix; P@V single mma (P tf32, no compensation).
// ============================================================================
#define RC      32
#define SPW     36
#define QSW     68

// smem layout (float units)
#define OFF_QS    0
#define OFF_KS0   4352
#define OFF_KS1   6528
#define OFF_VH0   8704
#define OFF_VH1   10880
#define OFF_SP    13056
#define OFF_TS    15360
#define OFF_MS    16448
#define OFF_SU    16512
#define OFF_SC    16576
#define SMEM_FLOATS 16640                 // 66560 B

__global__ __launch_bounds__(256, 3) void fused_attn_kernel(float* __restrict__ out)
{
    extern __shared__ float sm[];
    float* Qs = sm + OFF_QS;
    float* Sp = sm + OFF_SP;
    float* m_state   = sm + OFF_MS;
    float* sum_state = sm + OFF_SU;
    float* scalef    = sm + OFF_SC;

    const int tid  = threadIdx.x;
    const int lane = tid & 31;
    const int warp = tid >> 5;
    const int bh   = blockIdx.y;
    const int l0   = blockIdx.x * 64;

    const int mstrip = (warp & 3) * 16;
    const int nh2    = (warp >> 2) * 16;
    const int nhpv   = (warp >> 2) * 32;
    const int arow   = mstrip + (lane >> 2);
    const int kcl    = lane & 3;

    // ---- prologue: Q tile (tf32 bits) -> smem ----
#pragma unroll
    for (int i = 0; i < 4; i++) {
        const int idx = tid + i * 256;
        const int row = idx >> 4;
        const int c4  = idx & 15;
        *(float4*)&Qs[row * QSW + c4 * 4] =
            *(const float4*)(g_q + ((size_t)bh * LL + l0 + row) * DD + c4 * 4);
    }
    if (tid < 64) { m_state[tid] = -1e30f; sum_state[tid] = 0.f; }

    const int krow = tid >> 4, kseg = tid & 15;
    const int trow = tid >> 3, tseg = tid & 7;
    const int bql  = tid >> 2, bqc  = (tid & 3) * 8;

    const int a_lm_row = mstrip + ((lane >> 3) & 1) * 8 + (lane & 7);
    const int a_lm_col = ((lane >> 4) & 1) * 4;
    const int b_lm_row = nh2 + ((lane >> 4) & 1) * 8 + (lane & 7);
    const int b_lm_col = ((lane >> 3) & 1) * 4;
    const unsigned qa_lm = s2u(&Qs[a_lm_row * QSW + a_lm_col]);

    auto stage = [&](int rc, int db) {
        float* Ks = sm + (db ? OFF_KS1 : OFF_KS0);
        float* Vh = sm + (db ? OFF_VH1 : OFF_VH0);
#pragma unroll
        for (int i = 0; i < 2; i++) {
            const int row = krow + i * 16;
            const size_t goff = ((size_t)bh * LL + rc + row) * DD + kseg * 4;
            cp16(&Ks[row * QSW + kseg * 4], g_k + goff);
            cp16(&Vh[row * QSW + kseg * 4], g_v + goff);
        }
        asm volatile("cp.async.commit_group;" ::: "memory");
    };
    auto ldg_ts = [&](int rc) -> uint4 {
        return *(const uint4*)(g_biaskT + ((size_t)bh * LL + rc + trow) * LL + l0 + tseg * 8);
    };
    auto ldg_bq = [&](int rc) -> uint4 {
        return *(const uint4*)(g_biasq + ((size_t)bh * LL + l0 + bql) * LL + rc + bqc);
    };

    float accpv[4][4];
#pragma unroll
    for (int i = 0; i < 4; i++)
#pragma unroll
        for (int j = 0; j < 4; j++) accpv[i][j] = 0.f;

    uint4 ts_reg = ldg_ts(0);
    uint4 bq_reg = ldg_bq(0);
    stage(0, 0);

    for (int ci = 0; ci < LL / RC; ci++) {
        const int cur = ci & 1;
        float* Ks = sm + (cur ? OFF_KS1 : OFF_KS0);
        float* Vh = sm + (cur ? OFF_VH1 : OFF_VH0);
        unsigned short* TsL = (unsigned short*)(sm + OFF_TS);

        // TsL writes safe pre-barrier (prior chunk's stats reads completed
        // before its pre-PV sync, which every thread has passed).
        {
            const unsigned short* h = (const unsigned short*)&ts_reg;
#pragma unroll
            for (int j = 0; j < 8; j++)
                TsL[(tseg * 8 + j) * 34 + trow] = h[j];
        }

        asm volatile("cp.async.wait_group 0;" ::: "memory");
        __syncthreads();

        uint4 ts_next, bq_next;
        if (ci + 1 < LL / RC) {
            ts_next = ldg_ts((ci + 1) * RC);
            bq_next = ldg_bq((ci + 1) * RC);
            stage((ci + 1) * RC, cur ^ 1);
        }

        // ---- qk mma via ldmatrix ----
        float accqk[2][4];
#pragma unroll
        for (int i = 0; i < 2; i++)
#pragma unroll
            for (int j = 0; j < 4; j++) accqk[i][j] = 0.f;
        const unsigned kb_lm = s2u(&Ks[b_lm_row * QSW + b_lm_col]);
#pragma unroll
        for (int ks = 0; ks < 8; ks++) {
            unsigned a0, a1, a2, a3, b0, b1, c0, c1;
            ldsm4(a0, a1, a2, a3, qa_lm + ks * 32);
            ldsm4(b0, b1, c0, c1, kb_lm + ks * 32);
            mma_tf32(accqk[0][0], accqk[0][1], accqk[0][2], accqk[0][3],
                     a0, a1, a2, a3, b0, b1);
            mma_tf32(accqk[1][0], accqk[1][1], accqk[1][2], accqk[1][3],
                     a0, a1, a2, a3, c0, c1);
        }
#pragma unroll
        for (int nt = 0; nt < 2; nt++) {
            const int col = nh2 + nt * 8 + 2 * (lane & 3);
#pragma unroll
            for (int half = 0; half < 2; half++) {
                const int row = arow + half * 8;
                *(float2*)&Sp[row * SPW + col] =
                    make_float2(accqk[nt][2 * half + 0], accqk[nt][2 * half + 1]);
            }
        }
        __syncthreads();                    // Sp + TsL ready

        // ---- merged stats + P (tf32, no residual) ----
        {
            const int l  = bql;
            const int c0 = bqc;
            const float mv_old = m_state[l];
            float s[8];
            {
                float4 sp0 = *(float4*)&Sp[l * SPW + c0];
                float4 sp1 = *(float4*)&Sp[l * SPW + c0 + 4];
                const __nv_bfloat162* ts2 = (const __nv_bfloat162*)&TsL[l * 34 + c0];
                float2 b0 = bf2(bq_reg.x);
                float2 b1 = bf2(bq_reg.y);
                float2 b2 = bf2(bq_reg.z);
                float2 b3 = bf2(bq_reg.w);
                float2 t0 = __bfloat1622float2(ts2[0]);
                float2 t1 = __bfloat1622float2(ts2[1]);
                float2 t2 = __bfloat1622float2(ts2[2]);
                float2 t3 = __bfloat1622float2(ts2[3]);
                s[0] = sp0.x + b0.x + t0.x;  s[1] = sp0.y + b0.y + t0.y;
                s[2] = sp0.z + b1.x + t1.x;  s[3] = sp0.w + b1.y + t1.y;
                s[4] = sp1.x + b2.x + t2.x;  s[5] = sp1.y + b2.y + t2.y;
                s[6] = sp1.z + b3.x + t3.x;  s[7] = sp1.w + b3.y + t3.y;
            }
            float mc = s[0];
#pragma unroll
            for (int j = 1; j < 8; j++) mc = fmaxf(mc, s[j]);
            mc = fmaxf(mc, __shfl_xor_sync(0xffffffffu, mc, 1));
            mc = fmaxf(mc, __shfl_xor_sync(0xffffffffu, mc, 2));
            const float mnew = fmaxf(mv_old, mc);
            float e = 0.f;
            float pv[8];
#pragma unroll
            for (int j = 0; j < 8; j++) {
                pv[j] = __expf(s[j] - mnew);
                e += pv[j];
            }
            float4 p0, p1;
            p0.x = __uint_as_float(tf32cvt(pv[0]));
            p0.y = __uint_as_float(tf32cvt(pv[1]));
            p0.z = __uint_as_float(tf32cvt(pv[2]));
            p0.w = __uint_as_float(tf32cvt(pv[3]));
            p1.x = __uint_as_float(tf32cvt(pv[4]));
            p1.y = __uint_as_float(tf32cvt(pv[5]));
            p1.z = __uint_as_float(tf32cvt(pv[6]));
            p1.w = __uint_as_float(tf32cvt(pv[7]));
            *(float4*)&Sp[l * SPW + c0]     = p0;
            *(float4*)&Sp[l * SPW + c0 + 4] = p1;
            e += __shfl_xor_sync(0xffffffffu, e, 1);
            e += __shfl_xor_sync(0xffffffffu, e, 2);
            if ((tid & 3) == 0) {
                const float sc = __expf(mv_old - mnew);
                scalef[l] = sc;
                sum_state[l] = sum_state[l] * sc + e;
                m_state[l] = mnew;
            }
        }
        __syncthreads();                    // P + scalef ready

        // ---- rescale + P@V mma ----
        {
            const float sc0 = scalef[arow];
            const float sc1 = scalef[arow + 8];
#pragma unroll
            for (int nt = 0; nt < 4; nt++) {
                accpv[nt][0] *= sc0; accpv[nt][1] *= sc0;
                accpv[nt][2] *= sc1; accpv[nt][3] *= sc1;
            }
        }
#pragma unroll
        for (int ks = 0; ks < 4; ks++) {
            const int kc = ks * 8 + kcl;
            unsigned ah0 = __float_as_uint(Sp[arow * SPW + kc]);
            unsigned ah1 = __float_as_uint(Sp[(arow + 8) * SPW + kc]);
            unsigned ah2 = __float_as_uint(Sp[arow * SPW + kc + 4]);
            unsigned ah3 = __float_as_uint(Sp[(arow + 8) * SPW + kc + 4]);
#pragma unroll
            for (int nt = 0; nt < 4; nt++) {
                const int nb = nhpv + nt * 8 + (lane >> 2);
                unsigned bh0 = __float_as_uint(Vh[(ks * 8 + kcl) * QSW + nb]);
                unsigned bh1 = __float_as_uint(Vh[(ks * 8 + kcl + 4) * QSW + nb]);
                mma_tf32(accpv[nt][0], accpv[nt][1], accpv[nt][2], accpv[nt][3],
                         ah0, ah1, ah2, ah3, bh0, bh1);
            }
        }
        ts_reg = ts_next;
        bq_reg = bq_next;
    }

    // ---- write out[b, l, h*64 + d] ----
    const int b_idx = bh / HH;
    const int h     = bh % HH;
#pragma unroll
    for (int half = 0; half < 2; half++) {
        const int row = arow + half * 8;
        const float inv = 1.f / sum_state[row];
        const int l = l0 + row;
#pragma unroll
        for (int nt = 0; nt < 4; nt++) {
            const int col = nhpv + nt * 8 + 2 * (lane & 3);
            float2 r;
            r.x = accpv[nt][2 * half + 0] * inv;
            r.y = accpv[nt][2 * half + 1] * inv;
            *(float2*)&out[((size_t)(b_idx * LL + l)) * HIDD + h * DD + col] = r;
        }
    }
}

// ============================================================================
// launch — (q->bias0) || (k->bias1) || v, then fused.
// ============================================================================
extern "C" void kernel_launch(void* const* d_in, const int* in_sizes, int n_in,
                              void* d_out, int out_size)
{
    (void)in_sizes; (void)n_in; (void)out_size;
    const float* hidden = (const float*)d_in[0];
    const float* mask   = (const float*)d_in[1];
    const float* S      = (const float*)d_in[2];
    const float* Wq     = (const float*)d_in[3];
    const float* bq     = (const float*)d_in[4];
    const float* Wk     = (const float*)d_in[5];
    const float* bk     = (const float*)d_in[6];
    const float* Wv     = (const float*)d_in[7];
    const float* bv     = (const float*)d_in[8];
    float* out = (float*)d_out;

    static cudaStream_t s1 = 0, s2 = 0;
    static cudaEvent_t eR = 0, e1 = 0, e2 = 0;
    static int init_done = 0;
    if (!init_done) {
        cudaFuncSetAttribute(fused_attn_kernel,
                             cudaFuncAttributeMaxDynamicSharedMemorySize,
                             SMEM_FLOATS * (int)sizeof(float));
        cudaStreamCreateWithFlags(&s1, cudaStreamNonBlocking);
        cudaStreamCreateWithFlags(&s2, cudaStreamNonBlocking);
        cudaEventCreateWithFlags(&eR, cudaEventDisableTiming);
        cudaEventCreateWithFlags(&e1, cudaEventDisableTiming);
        cudaEventCreateWithFlags(&e2, cudaEventDisableTiming);
        init_done = 1;
    }

    dim3 g1(64, 12);
    dim3 g2(16, 1024);

    cudaEventRecord(eR, 0);
    cudaStreamWaitEvent(s1, eR, 0);
    cudaStreamWaitEvent(s2, eR, 0);

    // chain A (stream 0): q proj -> q-side bias
    qkv_mma_kernel<<<g1, 256, 0, 0>>>(hidden, Wq, bq, 0);
    bias_mma_kernel<<<g2, 256, 0, 0>>>(S, mask, 0);

    // chain B (s1): k proj -> k-side bias
    qkv_mma_kernel<<<g1, 256, 0, s1>>>(hidden, Wk, bk, 1);
    bias_mma_kernel<<<g2, 256, 0, s1>>>(S, mask, 1);

    // chain C (s2): v proj
    qkv_mma_kernel<<<g1, 256, 0, s2>>>(hidden, Wv, bv, 2);

    cudaEventRecord(e1, s1);
    cudaEventRecord(e2, s2);
    cudaStreamWaitEvent(0, e1, 0);
    cudaStreamWaitEvent(0, e2, 0);

    dim3 g3(16, 48);
    fused_attn_kernel<<<g3, 256, SMEM_FLOATS * sizeof(float)>>>(out);
}

// round 16
// speedup vs baseline: 1.1107x; 1.0001x over previous
#include <cuda_runtime.h>
#include <cuda_bf16.h>
#include <math.h>

#define BB   4
#define LL   1024
#define HIDD 768
#define HH   12
#define DD   64
#define BH   (BB*HH)

// ---- scratch (device globals; no allocation allowed) ----
__device__ float g_q[BH * LL * DD];                        // [bh, l, d] tf32 bits (pre-scaled 0.125)
__device__ float g_k[BH * LL * DD];                        // [bh, l, d] tf32 bits
__device__ float g_v[BH * LL * DD];                        // [bh, l, d] tf32 bits
__device__ __nv_bfloat16 g_biasq[(size_t)BH * LL * LL];    // [bh, l, r] = qS/8 + mask
__device__ __nv_bfloat16 g_biaskT[(size_t)BH * LL * LL];   // [bh, r, l] = kS/8

// ---------------- helpers ----------------
__device__ __forceinline__ unsigned tf32cvt(float x) {
    unsigned u;
    asm("cvt.rna.tf32.f32 %0, %1;" : "=r"(u) : "f"(x));
    return u;
}
__device__ __forceinline__ void mma_tf32(float& c0, float& c1, float& c2, float& c3,
                                         unsigned a0, unsigned a1, unsigned a2, unsigned a3,
                                         unsigned b0, unsigned b1) {
    asm("mma.sync.aligned.m16n8k8.row.col.f32.tf32.tf32.f32 "
        "{%0,%1,%2,%3},{%4,%5,%6,%7},{%8,%9},{%0,%1,%2,%3};"
        : "+f"(c0), "+f"(c1), "+f"(c2), "+f"(c3)
        : "r"(a0), "r"(a1), "r"(a2), "r"(a3), "r"(b0), "r"(b1));
}
__device__ __forceinline__ void cp16(const void* smem_dst, const void* gsrc) {
    unsigned sa = (unsigned)__cvta_generic_to_shared(smem_dst);
    asm volatile("cp.async.cg.shared.global [%0], [%1], 16;" :: "r"(sa), "l"(gsrc));
}
__device__ __forceinline__ float2 bf2(unsigned u) {
    __nv_bfloat162 h = *reinterpret_cast<__nv_bfloat162*>(&u);
    return __bfloat1622float2(h);
}
__device__ __forceinline__ unsigned s2u(const void* p) {
    return (unsigned)__cvta_generic_to_shared(p);
}
// ldmatrix x4: four 8x4-tf32 tiles; lane L supplies address for tile L>>3, row L&7.
__device__ __forceinline__ void ldsm4(unsigned& r0, unsigned& r1, unsigned& r2, unsigned& r3,
                                      unsigned saddr) {
    asm volatile("ldmatrix.sync.aligned.m8n8.x4.shared.b16 {%0,%1,%2,%3}, [%4];"
        : "=r"(r0), "=r"(r1), "=r"(r2), "=r"(r3) : "r"(saddr));
}

// ============================================================================
// K1: QKV projection, tf32 mma, register double-buffered staging.
// ============================================================================
__global__ __launch_bounds__(256) void qkv_mma_kernel(
    const float* __restrict__ X,
    const float* __restrict__ W,
    const float* __restrict__ bias,
    int which)
{
    __shared__ __align__(16) unsigned Xs[64][68];
    __shared__ __align__(16) unsigned Ws[64][68];

    const int tid  = threadIdx.x;
    const int warp = tid >> 5;
    const int lane = tid & 31;
    const int m0 = blockIdx.x * 64;
    const int n0 = blockIdx.y * 64;
    const int mstrip = (warp & 3) * 16;
    const int nh     = (warp >> 2) * 32;

    float acc[4][4];
#pragma unroll
    for (int i = 0; i < 4; i++)
#pragma unroll
        for (int j = 0; j < 4; j++) acc[i][j] = 0.f;

    float4 xr[4], wr[4];
#pragma unroll
    for (int i = 0; i < 4; i++) {
        const int idx = tid + i * 256;
        const int row = idx >> 4;
        const int c4  = idx & 15;
        xr[i] = *(const float4*)(X + (size_t)(m0 + row) * HIDD + c4 * 4);
        wr[i] = *(const float4*)(W + (size_t)(n0 + row) * HIDD + c4 * 4);
    }

    const unsigned a_lm = s2u(&Xs[mstrip + ((lane >> 3) & 1) * 8 + (lane & 7)]
                                 [((lane >> 4) & 1) * 4]);
    unsigned b_lm[2];
#pragma unroll
    for (int p = 0; p < 2; p++)
        b_lm[p] = s2u(&Ws[nh + p * 16 + ((lane >> 4) & 1) * 8 + (lane & 7)]
                         [((lane >> 3) & 1) * 4]);

    for (int k0 = 0; k0 < HIDD; k0 += 64) {
        __syncthreads();
#pragma unroll
        for (int i = 0; i < 4; i++) {
            const int idx = tid + i * 256;
            const int row = idx >> 4;
            const int c4  = idx & 15;
            Xs[row][c4 * 4 + 0] = tf32cvt(xr[i].x); Xs[row][c4 * 4 + 1] = tf32cvt(xr[i].y);
            Xs[row][c4 * 4 + 2] = tf32cvt(xr[i].z); Xs[row][c4 * 4 + 3] = tf32cvt(xr[i].w);
            Ws[row][c4 * 4 + 0] = tf32cvt(wr[i].x); Ws[row][c4 * 4 + 1] = tf32cvt(wr[i].y);
            Ws[row][c4 * 4 + 2] = tf32cvt(wr[i].z); Ws[row][c4 * 4 + 3] = tf32cvt(wr[i].w);
        }
        __syncthreads();
        if (k0 + 64 < HIDD) {
#pragma unroll
            for (int i = 0; i < 4; i++) {
                const int idx = tid + i * 256;
                const int row = idx >> 4;
                const int c4  = idx & 15;
                xr[i] = *(const float4*)(X + (size_t)(m0 + row) * HIDD + k0 + 64 + c4 * 4);
                wr[i] = *(const float4*)(W + (size_t)(n0 + row) * HIDD + k0 + 64 + c4 * 4);
            }
        }
#pragma unroll
        for (int ks = 0; ks < 8; ks++) {
            unsigned a0, a1, a2, a3;
            ldsm4(a0, a1, a2, a3, a_lm + ks * 32);
#pragma unroll
            for (int p = 0; p < 2; p++) {
                unsigned b0, b1, c0, c1;
                ldsm4(b0, b1, c0, c1, b_lm[p] + ks * 32);
                mma_tf32(acc[2 * p][0], acc[2 * p][1], acc[2 * p][2], acc[2 * p][3],
                         a0, a1, a2, a3, b0, b1);
                mma_tf32(acc[2 * p + 1][0], acc[2 * p + 1][1], acc[2 * p + 1][2], acc[2 * p + 1][3],
                         a0, a1, a2, a3, c0, c1);
            }
        }
    }

    float* out = (which == 0) ? g_q : (which == 1) ? g_k : g_v;
    const float scale = (which == 0) ? 0.125f : 1.0f;
    const int row0 = m0 + mstrip + (lane >> 2);
#pragma unroll
    for (int nt = 0; nt < 4; nt++) {
        const int col = n0 + nh + nt * 8 + 2 * (lane & 3);
        const int h = col >> 6;
        const int d = col & 63;
#pragma unroll
        for (int half = 0; half < 2; half++) {
            const int row = row0 + half * 8;
            const int b_idx = row >> 10;
            const int l     = row & (LL - 1);
            float2 r;
            r.x = __uint_as_float(tf32cvt((acc[nt][2 * half + 0] + bias[col + 0]) * scale));
            r.y = __uint_as_float(tf32cvt((acc[nt][2 * half + 1] + bias[col + 1]) * scale));
            *(float2*)&out[(((size_t)b_idx * HH + h) * LL + l) * DD + d] = r;
        }
    }
}

// ============================================================================
// K2: structure-bias GEMM (round-15 winner: 64-wide, cp.async, ldmatrix,
// staged coalesced __stcs stores, high occupancy).
// ============================================================================
#define STGW2 72   // staging stride in bf16 (144 B)

__global__ __launch_bounds__(256, 5) void bias_mma_kernel(
    const float* __restrict__ S, const float* __restrict__ mask, int variant)
{
    __shared__ __align__(16) unsigned As[64][68];
    __shared__ __align__(16) unsigned Ss[64][68];   // raw fp32 S; reused as bf16 staging

    const int tid  = threadIdx.x;
    const int warp = tid >> 5;
    const int lane = tid & 31;
    const int n0 = blockIdx.x * 64;
    const int f  = blockIdx.y;
    const int mstrip = (warp & 3) * 16;
    const int nh     = (warp >> 2) * 32;
    const int arow   = mstrip + (lane >> 2);

    const float* Aop = (variant == 0) ? g_q : g_k;

#pragma unroll
    for (int i = 0; i < 4; i++) {
        const int idx = tid + i * 256;
        const int row = idx >> 4;
        const int c4  = idx & 15;
        size_t soff = (variant == 0)
            ? (((size_t)f * LL + n0 + row) * DD + c4 * 4)
            : (((size_t)(n0 + row) * LL + f) * DD + c4 * 4);
        cp16(&Ss[row][c4 * 4], S + soff);
    }
    asm volatile("cp.async.commit_group;" ::: "memory");

#pragma unroll
    for (int i = 0; i < 4; i++) {
        const int idx = tid + i * 256;
        const int row = idx >> 4;
        const int c4  = idx & 15;
        if (row < BH) {
            float4 av = *(const float4*)(Aop + ((size_t)row * LL + f) * DD + c4 * 4);
            As[row][c4 * 4 + 0] = __float_as_uint(av.x);
            As[row][c4 * 4 + 1] = __float_as_uint(av.y);
            As[row][c4 * 4 + 2] = __float_as_uint(av.z);
            As[row][c4 * 4 + 3] = __float_as_uint(av.w);
        } else {
            As[row][c4 * 4 + 0] = 0u; As[row][c4 * 4 + 1] = 0u;
            As[row][c4 * 4 + 2] = 0u; As[row][c4 * 4 + 3] = 0u;
        }
    }

    asm volatile("cp.async.wait_group 0;" ::: "memory");
    __syncthreads();

    float acc[4][4];
#pragma unroll
    for (int i = 0; i < 4; i++)
#pragma unroll
        for (int j = 0; j < 4; j++) acc[i][j] = 0.f;

    const unsigned a_lm = s2u(&As[mstrip + ((lane >> 3) & 1) * 8 + (lane & 7)]
                                 [((lane >> 4) & 1) * 4]);
    unsigned b_lm[2];
#pragma unroll
    for (int p = 0; p < 2; p++)
        b_lm[p] = s2u(&Ss[nh + p * 16 + ((lane >> 4) & 1) * 8 + (lane & 7)]
                         [((lane >> 3) & 1) * 4]);

#pragma unroll
    for (int ks = 0; ks < 8; ks++) {
        unsigned a0, a1, a2, a3;
        ldsm4(a0, a1, a2, a3, a_lm + ks * 32);
#pragma unroll
        for (int p = 0; p < 2; p++) {
            unsigned b0, b1, c0, c1;
            ldsm4(b0, b1, c0, c1, b_lm[p] + ks * 32);
            b0 = tf32cvt(__uint_as_float(b0)); b1 = tf32cvt(__uint_as_float(b1));
            c0 = tf32cvt(__uint_as_float(c0)); c1 = tf32cvt(__uint_as_float(c1));
            mma_tf32(acc[2 * p][0], acc[2 * p][1], acc[2 * p][2], acc[2 * p][3],
                     a0, a1, a2, a3, b0, b1);
            mma_tf32(acc[2 * p + 1][0], acc[2 * p + 1][1], acc[2 * p + 1][2], acc[2 * p + 1][3],
                     a0, a1, a2, a3, c0, c1);
        }
    }
    __syncthreads();   // mma reads of Ss done; reuse as staging

    __nv_bfloat16* stg = (__nv_bfloat16*)&Ss[0][0];
#pragma unroll
    for (int nt = 0; nt < 4; nt++) {
        const int col = nh + nt * 8 + 2 * (lane & 3);
#pragma unroll
        for (int half = 0; half < 2; half++) {
            const int bh = arow + half * 8;
            if (bh >= BH) continue;
            __nv_bfloat162 bv;
            if (variant == 0) {
                const int b_idx = bh / HH;
                bv = __floats2bfloat162_rn(
                    acc[nt][2 * half + 0] + mask[b_idx * LL + n0 + col + 0],
                    acc[nt][2 * half + 1] + mask[b_idx * LL + n0 + col + 1]);
            } else {
                bv = __floats2bfloat162_rn(
                    acc[nt][2 * half + 0] * 0.125f,
                    acc[nt][2 * half + 1] * 0.125f);
            }
            *(__nv_bfloat162*)&stg[bh * STGW2 + col] = bv;
        }
    }
    __syncthreads();

    __nv_bfloat16* dst_base = (variant == 0) ? g_biasq : g_biaskT;
    if (tid < 192) {
#pragma unroll
        for (int i = 0; i < 2; i++) {
            const int idx = tid + i * 192;
            const int row = idx >> 3;             // bh 0..47
            const int seg = idx & 7;
            uint4 v = *(const uint4*)&stg[row * STGW2 + seg * 8];
            __stcs((uint4*)&dst_base[((size_t)row * LL + f) * LL + n0 + seg * 8], v);
        }
    }
}

// ============================================================================
// K3: fused flash attention, software-pipelined: 2 barriers/chunk,
// PV(i) overlapped with qk(i+1).  75.8 KB smem, 3 CTAs/SM.
// ============================================================================
#define RC      32
#define NCHUNK  (LL / RC)
#define SPW     36
#define QSW     68

// smem layout (float units)
#define OFF_QS    0
#define OFF_KS0   4352
#define OFF_KS1   6528
#define OFF_VH0   8704
#define OFF_VH1   10880
#define OFF_SP    13056
#define OFF_PB    15360
#define OFF_TS    17664
#define OFF_MS    18752
#define OFF_SU    18816
#define OFF_SC    18880
#define SMEM_FLOATS 18944                 // 75776 B

__global__ __launch_bounds__(256, 3) void fused_attn_kernel(float* __restrict__ out)
{
    extern __shared__ float sm[];
    float* Qs = sm + OFF_QS;
    float* Sp = sm + OFF_SP;
    float* Pb = sm + OFF_PB;
    float* m_state   = sm + OFF_MS;
    float* sum_state = sm + OFF_SU;
    float* scalef    = sm + OFF_SC;

    const int tid  = threadIdx.x;
    const int lane = tid & 31;
    const int warp = tid >> 5;
    const int bh   = blockIdx.y;
    const int l0   = blockIdx.x * 64;

    const int mstrip = (warp & 3) * 16;
    const int nh2    = (warp >> 2) * 16;
    const int nhpv   = (warp >> 2) * 32;
    const int arow   = mstrip + (lane >> 2);
    const int kcl    = lane & 3;

    // staging index decomposition
    const int krow = tid >> 4, kseg = tid & 15;
    const int trow = tid >> 3, tseg = tid & 7;
    const int bql  = tid >> 2, bqc  = (tid & 3) * 8;

    // ldmatrix per-thread offsets
    const int a_lm_row = mstrip + ((lane >> 3) & 1) * 8 + (lane & 7);
    const int a_lm_col = ((lane >> 4) & 1) * 4;
    const int b_lm_row = nh2 + ((lane >> 4) & 1) * 8 + (lane & 7);
    const int b_lm_col = ((lane >> 3) & 1) * 4;
    const unsigned qa_lm = s2u(&Qs[a_lm_row * QSW + a_lm_col]);

    auto stageK = [&](int rc, int db) {
        float* Ks = sm + (db ? OFF_KS1 : OFF_KS0);
#pragma unroll
        for (int i = 0; i < 2; i++) {
            const int row = krow + i * 16;
            cp16(&Ks[row * QSW + kseg * 4],
                 g_k + ((size_t)bh * LL + rc + row) * DD + kseg * 4);
        }
    };
    auto stageV = [&](int rc, int db) {
        float* Vh = sm + (db ? OFF_VH1 : OFF_VH0);
#pragma unroll
        for (int i = 0; i < 2; i++) {
            const int row = krow + i * 16;
            cp16(&Vh[row * QSW + kseg * 4],
                 g_v + ((size_t)bh * LL + rc + row) * DD + kseg * 4);
        }
    };
    auto ldg_ts = [&](int rc) -> uint4 {
        return *(const uint4*)(g_biaskT + ((size_t)bh * LL + rc + trow) * LL + l0 + tseg * 8);
    };
    auto ldg_bq = [&](int rc) -> uint4 {
        return *(const uint4*)(g_biasq + ((size_t)bh * LL + l0 + bql) * LL + rc + bqc);
    };
    auto ts_store = [&](uint4 t) {
        unsigned short* TsL = (unsigned short*)(sm + OFF_TS);
        const unsigned short* h = (const unsigned short*)&t;
#pragma unroll
        for (int j = 0; j < 8; j++)
            TsL[(tseg * 8 + j) * 34 + trow] = h[j];
    };
    auto qk_phase = [&](int i) {   // compute qk for chunk i -> Sp
        float* Ks = sm + ((i & 1) ? OFF_KS1 : OFF_KS0);
        float accqk[2][4];
#pragma unroll
        for (int a = 0; a < 2; a++)
#pragma unroll
            for (int j = 0; j < 4; j++) accqk[a][j] = 0.f;
        const unsigned kb_lm = s2u(&Ks[b_lm_row * QSW + b_lm_col]);
#pragma unroll
        for (int ks = 0; ks < 8; ks++) {
            unsigned a0, a1, a2, a3, b0, b1, c0, c1;
            ldsm4(a0, a1, a2, a3, qa_lm + ks * 32);
            ldsm4(b0, b1, c0, c1, kb_lm + ks * 32);
            mma_tf32(accqk[0][0], accqk[0][1], accqk[0][2], accqk[0][3],
                     a0, a1, a2, a3, b0, b1);
            mma_tf32(accqk[1][0], accqk[1][1], accqk[1][2], accqk[1][3],
                     a0, a1, a2, a3, c0, c1);
        }
#pragma unroll
        for (int nt = 0; nt < 2; nt++) {
            const int col = nh2 + nt * 8 + 2 * (lane & 3);
#pragma unroll
            for (int half = 0; half < 2; half++) {
                const int row = arow + half * 8;
                *(float2*)&Sp[row * SPW + col] =
                    make_float2(accqk[nt][2 * half + 0], accqk[nt][2 * half + 1]);
            }
        }
    };

    // ---- prologue ----
#pragma unroll
    for (int i = 0; i < 4; i++) {
        const int idx = tid + i * 256;
        const int row = idx >> 4;
        const int c4  = idx & 15;
        *(float4*)&Qs[row * QSW + c4 * 4] =
            *(const float4*)(g_q + ((size_t)bh * LL + l0 + row) * DD + c4 * 4);
    }
    if (tid < 64) { m_state[tid] = -1e30f; sum_state[tid] = 0.f; }

    stageK(0, 0); stageV(0, 0);
    asm volatile("cp.async.commit_group;" ::: "memory");   // G0: K0,V0
    stageK(RC, 1);
    asm volatile("cp.async.commit_group;" ::: "memory");   // G1: K1

    ts_store(ldg_ts(0));                 // TsL(0)
    uint4 ts_reg = ldg_ts(RC);           // ts(1)
    uint4 bq_reg = ldg_bq(0);            // bq(0)

    float accpv[4][4];
#pragma unroll
    for (int i = 0; i < 4; i++)
#pragma unroll
        for (int j = 0; j < 4; j++) accpv[i][j] = 0.f;

    asm volatile("cp.async.wait_group 1;" ::: "memory");   // G0 done
    __syncthreads();                                       // K0/V0 + Qs + TsL(0) visible
    qk_phase(0);                                           // -> Sp(0)

    for (int ci = 0; ci < NCHUNK; ci++) {
        __syncthreads();                 // sync_a: Sp(ci) + TsL(ci) visible

        // ---- phase 1: stats(ci): Sp + TsL + bq -> Pb, scalef, m, sum ----
        {
            const int l  = bql;
            const int c0 = bqc;
            const float mv_old = m_state[l];
            const unsigned short* TsLl =
                (const unsigned short*)(sm + OFF_TS) + l * 34 + c0;
            float s[8];
            {
                float4 sp0 = *(float4*)&Sp[l * SPW + c0];
                float4 sp1 = *(float4*)&Sp[l * SPW + c0 + 4];
                const __nv_bfloat162* ts2 = (const __nv_bfloat162*)TsLl;
                float2 b0 = bf2(bq_reg.x);
                float2 b1 = bf2(bq_reg.y);
                float2 b2 = bf2(bq_reg.z);
                float2 b3 = bf2(bq_reg.w);
                float2 t0 = __bfloat1622float2(ts2[0]);
                float2 t1 = __bfloat1622float2(ts2[1]);
                float2 t2 = __bfloat1622float2(ts2[2]);
                float2 t3 = __bfloat1622float2(ts2[3]);
                s[0] = sp0.x + b0.x + t0.x;  s[1] = sp0.y + b0.y + t0.y;
                s[2] = sp0.z + b1.x + t1.x;  s[3] = sp0.w + b1.y + t1.y;
                s[4] = sp1.x + b2.x + t2.x;  s[5] = sp1.y + b2.y + t2.y;
                s[6] = sp1.z + b3.x + t3.x;  s[7] = sp1.w + b3.y + t3.y;
            }
            float mc = s[0];
#pragma unroll
            for (int j = 1; j < 8; j++) mc = fmaxf(mc, s[j]);
            mc = fmaxf(mc, __shfl_xor_sync(0xffffffffu, mc, 1));
            mc = fmaxf(mc, __shfl_xor_sync(0xffffffffu, mc, 2));
            const float mnew = fmaxf(mv_old, mc);
            float e = 0.f;
            float pv[8];
#pragma unroll
            for (int j = 0; j < 8; j++) {
                pv[j] = __expf(s[j] - mnew);
                e += pv[j];
            }
            float4 p0, p1;
            p0.x = __uint_as_float(tf32cvt(pv[0]));
            p0.y = __uint_as_float(tf32cvt(pv[1]));
            p0.z = __uint_as_float(tf32cvt(pv[2]));
            p0.w = __uint_as_float(tf32cvt(pv[3]));
            p1.x = __uint_as_float(tf32cvt(pv[4]));
            p1.y = __uint_as_float(tf32cvt(pv[5]));
            p1.z = __uint_as_float(tf32cvt(pv[6]));
            p1.w = __uint_as_float(tf32cvt(pv[7]));
            *(float4*)&Pb[l * SPW + c0]     = p0;
            *(float4*)&Pb[l * SPW + c0 + 4] = p1;
            e += __shfl_xor_sync(0xffffffffu, e, 1);
            e += __shfl_xor_sync(0xffffffffu, e, 2);
            if ((tid & 3) == 0) {
                const float sc = __expf(mv_old - mnew);
                scalef[l] = sc;
                sum_state[l] = sum_state[l] * sc + e;
                m_state[l] = mnew;
            }
        }
        if (ci + 1 < NCHUNK) bq_reg = ldg_bq((ci + 1) * RC);

        asm volatile("cp.async.wait_group 0;" ::: "memory");  // K(ci+1), V(ci) landed
        __syncthreads();                 // sync_b: staged data + Pb + scalef visible

        // ---- phase 2: stage next, TsL(ci+1), PV(ci) || qk(ci+1) ----
        {
            bool issued = false;
            if (ci + 2 < NCHUNK) { stageK((ci + 2) * RC, ci & 1); issued = true; }
            if (ci + 1 < NCHUNK) { stageV((ci + 1) * RC, (ci + 1) & 1); issued = true; }
            if (issued) asm volatile("cp.async.commit_group;" ::: "memory");
        }
        if (ci + 1 < NCHUNK) {
            ts_store(ts_reg);                             // TsL(ci+1)
            if (ci + 2 < NCHUNK) ts_reg = ldg_ts((ci + 2) * RC);
        }

        // rescale accpv
        {
            const float sc0 = scalef[arow];
            const float sc1 = scalef[arow + 8];
#pragma unroll
            for (int nt = 0; nt < 4; nt++) {
                accpv[nt][0] *= sc0; accpv[nt][1] *= sc0;
                accpv[nt][2] *= sc1; accpv[nt][3] *= sc1;
            }
        }

        if (ci + 1 < NCHUNK) qk_phase(ci + 1);            // -> Sp(ci+1)

        // PV(ci) from Pb and Vh[ci&1]
        {
            float* Vh = sm + ((ci & 1) ? OFF_VH1 : OFF_VH0);
#pragma unroll
            for (int ks = 0; ks < 4; ks++) {
                const int kc = ks * 8 + kcl;
                unsigned ah0 = __float_as_uint(Pb[arow * SPW + kc]);
                unsigned ah1 = __float_as_uint(Pb[(arow + 8) * SPW + kc]);
                unsigned ah2 = __float_as_uint(Pb[arow * SPW + kc + 4]);
                unsigned ah3 = __float_as_uint(Pb[(arow + 8) * SPW + kc + 4]);
#pragma unroll
                for (int nt = 0; nt < 4; nt++) {
                    const int nb = nhpv + nt * 8 + (lane >> 2);
                    unsigned bh0 = __float_as_uint(Vh[(ks * 8 + kcl) * QSW + nb]);
                    unsigned bh1 = __float_as_uint(Vh[(ks * 8 + kcl + 4) * QSW + nb]);
                    mma_tf32(accpv[nt][0], accpv[nt][1], accpv[nt][2], accpv[nt][3],
                             ah0, ah1, ah2, ah3, bh0, bh1);
                }
            }
        }
    }

    // ---- write out[b, l, h*64 + d] ----
    const int b_idx = bh / HH;
    const int h     = bh % HH;
#pragma unroll
    for (int half = 0; half < 2; half++) {
        const int row = arow + half * 8;
        const float inv = 1.f / sum_state[row];
        const int l = l0 + row;
#pragma unroll
        for (int nt = 0; nt < 4; nt++) {
            const int col = nhpv + nt * 8 + 2 * (lane & 3);
            float2 r;
            r.x = accpv[nt][2 * half + 0] * inv;
            r.y = accpv[nt][2 * half + 1] * inv;
            *(float2*)&out[((size_t)(b_idx * LL + l)) * HIDD + h * DD + col] = r;
        }
    }
}

// ============================================================================
// launch — (q->bias0) || (k->bias1) || v, then fused.
// ============================================================================
extern "C" void kernel_launch(void* const* d_in, const int* in_sizes, int n_in,
                              void* d_out, int out_size)
{
    (void)in_sizes; (void)n_in; (void)out_size;
    const float* hidden = (const float*)d_in[0];
    const float* mask   = (const float*)d_in[1];
    const float* S      = (const float*)d_in[2];
    const float* Wq     = (const float*)d_in[3];
    const float* bq     = (const float*)d_in[4];
    const float* Wk     = (const float*)d_in[5];
    const float* bk     = (const float*)d_in[6];
    const float* Wv     = (const float*)d_in[7];
    const float* bv     = (const float*)d_in[8];
    float* out = (float*)d_out;

    static cudaStream_t s1 = 0, s2 = 0;
    static cudaEvent_t eR = 0, e1 = 0, e2 = 0;
    static int init_done = 0;
    if (!init_done) {
        cudaFuncSetAttribute(fused_attn_kernel,
                             cudaFuncAttributeMaxDynamicSharedMemorySize,
                             SMEM_FLOATS * (int)sizeof(float));
        cudaStreamCreateWithFlags(&s1, cudaStreamNonBlocking);
        cudaStreamCreateWithFlags(&s2, cudaStreamNonBlocking);
        cudaEventCreateWithFlags(&eR, cudaEventDisableTiming);
        cudaEventCreateWithFlags(&e1, cudaEventDisableTiming);
        cudaEventCreateWithFlags(&e2, cudaEventDisableTiming);
        init_done = 1;
    }

    dim3 g1(64, 12);
    dim3 g2(16, 1024);

    cudaEventRecord(eR, 0);
    cudaStreamWaitEvent(s1, eR, 0);
    cudaStreamWaitEvent(s2, eR, 0);

    // chain A (stream 0): q proj -> q-side bias
    qkv_mma_kernel<<<g1, 256, 0, 0>>>(hidden, Wq, bq, 0);
    bias_mma_kernel<<<g2, 256, 0, 0>>>(S, mask, 0);

    // chain B (s1): k proj -> k-side bias
    qkv_mma_kernel<<<g1, 256, 0, s1>>>(hidden, Wk, bk, 1);
    bias_mma_kernel<<<g2, 256, 0, s1>>>(S, mask, 1);

    // chain C (s2): v proj
    qkv_mma_kernel<<<g1, 256, 0, s2>>>(hidden, Wv, bv, 2);

    cudaEventRecord(e1, s1);
    cudaEventRecord(e2, s2);
    cudaStreamWaitEvent(0, e1, 0);
    cudaStreamWaitEvent(0, e2, 0);

    dim3 g3(16, 48);
    fused_attn_kernel<<<g3, 256, SMEM_FLOATS * sizeof(float)>>>(out);
}